// round 1
// baseline (speedup 1.0000x reference)
#include <cuda_runtime.h>
#include <cuda_bf16.h>
#include <math.h>

// Problem constants
#define BB 2
#define SS 2048
#define EE 768
#define FF 3072
#define RR 4
#define TT 128
#define HH 12
#define HD 64
#define HID 128
#define MM (BB*SS)          // 4096 tokens

// ---------------- scratch (device globals; no cudaMalloc allowed) ----------
__device__ float g_x1  [MM*EE];        // rmsnorm1 output
__device__ float g_qkv [MM*3*EE];      // qkv projection
__device__ float g_ctx [MM*EE];        // attention context
__device__ float g_src2[MM*EE];        // residual after attention
__device__ float g_x2  [MM*EE];        // rmsnorm2 output
__device__ float g_hA  [MM*HID];       // hypernet A hidden
__device__ float g_hB  [MM*HID];       // hypernet B hidden
__device__ float g_WBt [(RR*HID+RR)*EE];   // [516,768] rearranged B weights (+bias rows)
__device__ float g_v   [MM*(RR*HID+RR)];   // [4096,516]
__device__ float g_int [MM*RR];        // inter [4096,4]
__device__ float g_u   [MM*RR*HID];    // [4096,512] inter x hA outer product
__device__ float g_h   [MM*FF];        // ffn hidden

// ---------------- rmsnorm --------------------------------------------------
__global__ void __launch_bounds__(256) rmsnorm_kernel(
    const float* __restrict__ x, const float* __restrict__ w, float* __restrict__ y)
{
    int row = blockIdx.x;
    const float* xr = x + (size_t)row * EE;
    float vals[3];
    float s = 0.f;
#pragma unroll
    for (int i = 0; i < 3; i++) {
        vals[i] = xr[threadIdx.x + i * 256];
        s += vals[i] * vals[i];
    }
#pragma unroll
    for (int o = 16; o; o >>= 1) s += __shfl_down_sync(0xffffffffu, s, o);
    __shared__ float red[8];
    if ((threadIdx.x & 31) == 0) red[threadIdx.x >> 5] = s;
    __syncthreads();
    if (threadIdx.x < 8) {
        float t = red[threadIdx.x];
#pragma unroll
        for (int o = 4; o; o >>= 1) t += __shfl_down_sync(0xffu, t, o);
        if (threadIdx.x == 0) red[0] = t;
    }
    __syncthreads();
    float r = rsqrtf(red[0] * (1.0f / EE) + 1.1920929e-7f);
    float* yr = y + (size_t)row * EE;
#pragma unroll
    for (int i = 0; i < 3; i++) {
        int c = threadIdx.x + i * 256;
        yr[c] = vals[i] * r * w[c];
    }
}

// ---------------- generic tiled SGEMM: C = A @ W^T (+epilogues) ------------
// A: [M,K] row-major, W: [N,K] row-major, C: [M,N]
// bias  (opt): [N]
// res   (opt): [M,N] added
// inter4/b2 (opt): adds sum_r inter4[m*4+r]*b2[n*4+r]
// relu flag
__global__ void __launch_bounds__(256) sgemm_nt(
    const float* __restrict__ A, const float* __restrict__ W,
    float* __restrict__ C,
    const float* __restrict__ bias, const float* __restrict__ res,
    const float* __restrict__ inter4, const float* __restrict__ b2,
    int M, int N, int K, int relu)
{
    __shared__ float As[16][132];
    __shared__ float Ws[16][132];
    const int bx = blockIdx.x, by = blockIdx.y;
    const int tid = threadIdx.x;
    const int tx = tid & 15, ty = tid >> 4;
    const int mBase = by * 128, nBase = bx * 128;

    const int lrow = tid >> 2;        // 0..63
    const int lc4  = (tid & 3) * 4;   // k offset 0,4,8,12

    float acc[8][8];
#pragma unroll
    for (int i = 0; i < 8; i++)
#pragma unroll
        for (int j = 0; j < 8; j++) acc[i][j] = 0.f;

    for (int k0 = 0; k0 < K; k0 += 16) {
#pragma unroll
        for (int half = 0; half < 2; half++) {
            int row = lrow + half * 64;
            float4 av = *(const float4*)(A + (size_t)(mBase + row) * K + k0 + lc4);
            As[lc4 + 0][row] = av.x; As[lc4 + 1][row] = av.y;
            As[lc4 + 2][row] = av.z; As[lc4 + 3][row] = av.w;
            int n = nBase + row;
            float4 wv = make_float4(0.f, 0.f, 0.f, 0.f);
            if (n < N) wv = *(const float4*)(W + (size_t)n * K + k0 + lc4);
            Ws[lc4 + 0][row] = wv.x; Ws[lc4 + 1][row] = wv.y;
            Ws[lc4 + 2][row] = wv.z; Ws[lc4 + 3][row] = wv.w;
        }
        __syncthreads();
#pragma unroll
        for (int k = 0; k < 16; k++) {
            float a[8], w[8];
#pragma unroll
            for (int i = 0; i < 8; i++) a[i] = As[k][ty * 8 + i];
#pragma unroll
            for (int j = 0; j < 8; j++) w[j] = Ws[k][tx * 8 + j];
#pragma unroll
            for (int i = 0; i < 8; i++)
#pragma unroll
                for (int j = 0; j < 8; j++) acc[i][j] += a[i] * w[j];
        }
        __syncthreads();
    }

#pragma unroll
    for (int i = 0; i < 8; i++) {
        int m = mBase + ty * 8 + i;
        float i0 = 0.f, i1 = 0.f, i2 = 0.f, i3 = 0.f;
        if (inter4) {
            const float* ip = inter4 + (size_t)m * 4;
            i0 = ip[0]; i1 = ip[1]; i2 = ip[2]; i3 = ip[3];
        }
#pragma unroll
        for (int j = 0; j < 8; j++) {
            int n = nBase + tx * 8 + j;
            if (n < N) {
                float v = acc[i][j];
                if (bias) v += bias[n];
                if (res)  v += res[(size_t)m * N + n];
                if (b2) {
                    const float* bp = b2 + (size_t)n * 4;
                    v += i0 * bp[0] + i1 * bp[1] + i2 * bp[2] + i3 * bp[3];
                }
                if (relu) v = fmaxf(v, 0.f);
                C[(size_t)m * N + n] = v;
            }
        }
    }
}

// ---------------- attention (online softmax, 1 thread = 1 query) -----------
__global__ void __launch_bounds__(128) attn_kernel(
    const float* __restrict__ qkv, float* __restrict__ ctx)
{
    const int qi = blockIdx.x * 128 + threadIdx.x;   // query pos in S
    const int h  = blockIdx.y;
    const int b  = blockIdx.z;

    const float* qptr = qkv + ((size_t)(b * SS + qi)) * (3 * EE) + h * HD;
    float q[HD];
#pragma unroll
    for (int d = 0; d < HD; d++) q[d] = qptr[d] * 0.125f;  // 1/sqrt(64)

    float o[HD];
#pragma unroll
    for (int d = 0; d < HD; d++) o[d] = 0.f;
    float mx = -INFINITY, l = 0.f;

    __shared__ float Ks[32][HD];
    __shared__ float Vs[32][HD];

    for (int k0 = 0; k0 < SS; k0 += 32) {
        __syncthreads();
        // 32 rows x 64 floats = 512 float4; 128 threads -> 4 each
#pragma unroll
        for (int it = 0; it < 4; it++) {
            int i = threadIdx.x + it * 128;
            int r = i >> 4, c4 = i & 15;
            const float* base = qkv + ((size_t)(b * SS + k0 + r)) * (3 * EE) + h * HD;
            ((float4*)Ks[r])[c4] = ((const float4*)(base + EE))[c4];
            ((float4*)Vs[r])[c4] = ((const float4*)(base + 2 * EE))[c4];
        }
        __syncthreads();
#pragma unroll 2
        for (int kk = 0; kk < 32; kk++) {
            float s = 0.f;
#pragma unroll
            for (int d = 0; d < HD; d++) s += q[d] * Ks[kk][d];
            if (s > mx) {
                float corr = __expf(mx - s);
                l *= corr;
#pragma unroll
                for (int d = 0; d < HD; d++) o[d] *= corr;
                mx = s;
            }
            float p = __expf(s - mx);
            l += p;
#pragma unroll
            for (int d = 0; d < HD; d++) o[d] += p * Vs[kk][d];
        }
    }
    float inv = 1.f / l;
    float* optr = ctx + ((size_t)(b * SS + qi)) * EE + h * HD;
#pragma unroll
    for (int d = 0; d < HD; d++) optr[d] = o[d] * inv;
}

// ---------------- small helper kernels -------------------------------------
// Build rearranged B-side weights: WBt[n][e]:
//   n < 512:  WBt[r*128+h][e] = hB_w2[(r*768+e)*128 + h]
//   n >= 512: WBt[512+r][e]   = hB_b2[r*768+e]
__global__ void build_WBt(const float* __restrict__ hB_w2,
                          const float* __restrict__ hB_b2,
                          float* __restrict__ WBt)
{
    int idx = blockIdx.x * 256 + threadIdx.x;
    if (idx >= (RR * HID + RR) * EE) return;
    int n = idx / EE, e = idx % EE;
    float val;
    if (n < RR * HID) {
        int r = n >> 7, h = n & 127;
        val = hB_w2[((size_t)(r * EE + e)) * HID + h];
    } else {
        val = hB_b2[(n - RR * HID) * EE + e];
    }
    WBt[idx] = val;
}

// inter[m,r] = sum_h hB[m,h] * v[m, r*128+h] + v[m, 512+r]
__global__ void inter_kernel(const float* __restrict__ v,
                             const float* __restrict__ hB,
                             float* __restrict__ inter)
{
    int warp = (blockIdx.x * blockDim.x + threadIdx.x) >> 5;
    int lane = threadIdx.x & 31;
    if (warp >= MM) return;
    const float* vr = v + (size_t)warp * (RR * HID + RR);
    const float* br = hB + (size_t)warp * HID;
#pragma unroll
    for (int r = 0; r < RR; r++) {
        float s = 0.f;
#pragma unroll
        for (int j = 0; j < 4; j++) {
            int hh = lane + j * 32;
            s += br[hh] * vr[r * HID + hh];
        }
#pragma unroll
        for (int o = 16; o; o >>= 1) s += __shfl_down_sync(0xffffffffu, s, o);
        if (lane == 0) inter[warp * RR + r] = s + vr[RR * HID + r];
    }
}

// u[m, r*128+h] = inter[m,r] * hA[m,h]
__global__ void u_kernel(const float* __restrict__ inter,
                         const float* __restrict__ hA,
                         float* __restrict__ u)
{
    int idx = blockIdx.x * 256 + threadIdx.x;
    if (idx >= MM * RR * HID) return;
    int m = idx >> 9;
    int c = idx & 511;
    int r = c >> 7;
    u[idx] = inter[m * RR + r] * hA[m * HID + (c & 127)];
}

// ---------------- launch ----------------------------------------------------
extern "C" void kernel_launch(void* const* d_in, const int* in_sizes, int n_in,
                              void* d_out, int out_size)
{
    const float* src       = (const float*)d_in[0];
    const float* task      = (const float*)d_in[1];
    const float* norm1_w   = (const float*)d_in[2];
    const float* norm2_w   = (const float*)d_in[3];
    const float* in_proj_w = (const float*)d_in[4];
    const float* out_proj_w= (const float*)d_in[5];
    const float* ffn1_w    = (const float*)d_in[6];
    const float* ffn1_b    = (const float*)d_in[7];
    const float* ffn2_w    = (const float*)d_in[8];
    const float* ffn2_b    = (const float*)d_in[9];
    const float* hA_w1     = (const float*)d_in[10];
    const float* hA_b1     = (const float*)d_in[11];
    const float* hA_w2     = (const float*)d_in[12];
    const float* hA_b2     = (const float*)d_in[13];
    const float* hB_w1     = (const float*)d_in[14];
    const float* hB_b1     = (const float*)d_in[15];
    const float* hB_w2     = (const float*)d_in[16];
    const float* hB_b2     = (const float*)d_in[17];
    float* out = (float*)d_out;

    float *x1, *qkv, *ctx, *src2, *x2, *hA, *hB, *WBt, *v, *inter, *u, *hbuf;
    cudaGetSymbolAddress((void**)&x1,   g_x1);
    cudaGetSymbolAddress((void**)&qkv,  g_qkv);
    cudaGetSymbolAddress((void**)&ctx,  g_ctx);
    cudaGetSymbolAddress((void**)&src2, g_src2);
    cudaGetSymbolAddress((void**)&x2,   g_x2);
    cudaGetSymbolAddress((void**)&hA,   g_hA);
    cudaGetSymbolAddress((void**)&hB,   g_hB);
    cudaGetSymbolAddress((void**)&WBt,  g_WBt);
    cudaGetSymbolAddress((void**)&v,    g_v);
    cudaGetSymbolAddress((void**)&inter,g_int);
    cudaGetSymbolAddress((void**)&u,    g_u);
    cudaGetSymbolAddress((void**)&hbuf, g_h);

    // 1) x1 = rmsnorm(src, norm1_w)
    rmsnorm_kernel<<<MM, 256>>>(src, norm1_w, x1);

    // 2) qkv = x1 @ in_proj_w^T   [4096, 2304]
    sgemm_nt<<<dim3((3 * EE + 127) / 128, MM / 128), 256>>>(
        x1, in_proj_w, qkv, nullptr, nullptr, nullptr, nullptr,
        MM, 3 * EE, EE, 0);

    // 3) attention -> ctx [4096, 768]
    attn_kernel<<<dim3(SS / 128, HH, BB), 128>>>(qkv, ctx);

    // 4) src2 = src + ctx @ out_proj_w^T
    sgemm_nt<<<dim3(EE / 128, MM / 128), 256>>>(
        ctx, out_proj_w, src2, nullptr, src, nullptr, nullptr,
        MM, EE, EE, 0);

    // 5) x2 = rmsnorm(src2, norm2_w)
    rmsnorm_kernel<<<MM, 256>>>(src2, norm2_w, x2);

    // 6) hypernet hiddens: hA = relu(task @ hA_w1^T + hA_b1), hB likewise
    sgemm_nt<<<dim3(1, MM / 128), 256>>>(
        task, hA_w1, hA, hA_b1, nullptr, nullptr, nullptr, MM, HID, TT, 1);
    sgemm_nt<<<dim3(1, MM / 128), 256>>>(
        task, hB_w1, hB, hB_b1, nullptr, nullptr, nullptr, MM, HID, TT, 1);

    // 7) rearrange B-side weights (incl. bias rows)
    build_WBt<<<((RR * HID + RR) * EE + 255) / 256, 256>>>(hB_w2, hB_b2, WBt);

    // 8) v = x2 @ WBt^T  [4096, 516]
    sgemm_nt<<<dim3((RR * HID + RR + 127) / 128, MM / 128), 256>>>(
        x2, WBt, v, nullptr, nullptr, nullptr, nullptr,
        MM, RR * HID + RR, EE, 0);

    // 9) inter[m,r]
    inter_kernel<<<(MM * 32 + 255) / 256, 256>>>(v, hB, inter);

    // 10) u = inter x hA outer product  [4096,512]
    u_kernel<<<(MM * RR * HID + 255) / 256, 256>>>(inter, hA, u);

    // 11) base = x2 @ ffn1_w^T + ffn1_b  -> hbuf
    sgemm_nt<<<dim3(FF / 128, MM / 128), 256>>>(
        x2, ffn1_w, hbuf, ffn1_b, nullptr, nullptr, nullptr,
        MM, FF, EE, 0);

    // 12) hbuf = relu(hbuf + u @ hA_w2_view^T + sum_r inter_r*hA_b2[f*4+r])
    //     hA_w2 [F*R, HID] row-major == [F, R*HID] view: perfect, no transpose.
    sgemm_nt<<<dim3(FF / 128, MM / 128), 256>>>(
        u, hA_w2, hbuf, nullptr, hbuf, inter, hA_b2,
        MM, FF, RR * HID, 1);

    // 13) out = src2 + hbuf @ ffn2_w^T + ffn2_b
    sgemm_nt<<<dim3(EE / 128, MM / 128), 256>>>(
        hbuf, ffn2_w, out, ffn2_b, src2, nullptr, nullptr,
        MM, EE, FF, 0);
}

// round 2
// speedup vs baseline: 1.8145x; 1.8145x over previous
#include <cuda_runtime.h>
#include <cuda_bf16.h>
#include <math.h>

// Problem constants
#define BB 2
#define SS 2048
#define EE 768
#define FF 3072
#define RR 4
#define TT 128
#define HH 12
#define HD 64
#define HID 128
#define MM (BB*SS)          // 4096 tokens

// ---------------- scratch (device globals; no cudaMalloc allowed) ----------
__device__ float g_x1  [MM*EE];
__device__ float g_qkv [MM*3*EE];
__device__ float g_ctx [MM*EE];
__device__ float g_src2[MM*EE];
__device__ float g_x2  [MM*EE];
__device__ float g_hA  [MM*HID];
__device__ float g_hB  [MM*HID];
__device__ float g_WBt [(RR*HID+RR)*EE];
__device__ float g_v   [MM*(RR*HID+RR)];
__device__ float g_int [MM*RR];
__device__ float g_u   [MM*RR*HID];
__device__ float g_h   [MM*FF];
__device__ float g_scores[(long long)BB*HH*SS*SS];   // 402 MB

// ---------------- helpers ---------------------------------------------------
__device__ __forceinline__ unsigned f2tf32(float f) {
    unsigned u;
    asm("cvt.rna.tf32.f32 %0, %1;" : "=r"(u) : "f"(f));
    return u;
}

__device__ __forceinline__ void mma_tf32(float c[4], const unsigned a[4], const unsigned b[2]) {
    asm volatile(
        "mma.sync.aligned.m16n8k8.row.col.f32.tf32.tf32.f32 "
        "{%0,%1,%2,%3}, {%4,%5,%6,%7}, {%8,%9}, {%0,%1,%2,%3};\n"
        : "+f"(c[0]), "+f"(c[1]), "+f"(c[2]), "+f"(c[3])
        : "r"(a[0]), "r"(a[1]), "r"(a[2]), "r"(a[3]), "r"(b[0]), "r"(b[1]));
}

// ---------------- rmsnorm --------------------------------------------------
__global__ void __launch_bounds__(256) rmsnorm_kernel(
    const float* __restrict__ x, const float* __restrict__ w, float* __restrict__ y)
{
    int row = blockIdx.x;
    const float* xr = x + (size_t)row * EE;
    float vals[3];
    float s = 0.f;
#pragma unroll
    for (int i = 0; i < 3; i++) {
        vals[i] = xr[threadIdx.x + i * 256];
        s += vals[i] * vals[i];
    }
#pragma unroll
    for (int o = 16; o; o >>= 1) s += __shfl_down_sync(0xffffffffu, s, o);
    __shared__ float red[8];
    if ((threadIdx.x & 31) == 0) red[threadIdx.x >> 5] = s;
    __syncthreads();
    if (threadIdx.x < 8) {
        float t = red[threadIdx.x];
#pragma unroll
        for (int o = 4; o; o >>= 1) t += __shfl_down_sync(0xffu, t, o);
        if (threadIdx.x == 0) red[0] = t;
    }
    __syncthreads();
    float r = rsqrtf(red[0] * (1.0f / EE) + 1.1920929e-7f);
    float* yr = y + (size_t)row * EE;
#pragma unroll
    for (int i = 0; i < 3; i++) {
        int c = threadIdx.x + i * 256;
        yr[c] = vals[i] * r * w[c];
    }
}

// ---------------- tf32 tensor-core GEMM -------------------------------------
// C = A @ op(B)  (+epilogues)
// flags bit0: relu, bit1: B is W[N,K] row-major (nt); else B is [K,N] row-major (nn)
// batched: blockIdx.z -> (zb = z/HH, zh = z%HH); ptr += zb*SB + zh*SH
__global__ void __launch_bounds__(256) mma_gemm(
    const float* __restrict__ A, const float* __restrict__ B, float* __restrict__ C,
    const float* __restrict__ bias, const float* __restrict__ res,
    const float* __restrict__ inter4, const float* __restrict__ b2,
    int M, int N, int K, int lda, int ldb, int ldc,
    long long aSB, long long aSH, long long bSB, long long bSH,
    long long cSB, long long cSH, int flags)
{
    const int zb = blockIdx.z / HH, zh = blockIdx.z % HH;
    A += zb * aSB + zh * aSH;
    B += zb * bSB + zh * bSH;
    C += zb * cSB + zh * cSH;
    if (res) res += zb * cSB + zh * cSH;

    __shared__ float As[32][132];
    __shared__ float Bs[32][132];

    const int tid  = threadIdx.x;
    const int lane = tid & 31, warp = tid >> 5;
    const int g = lane >> 2, t4 = lane & 3;
    const int wm = (warp >> 1) * 32;      // 0,32,64,96
    const int wn = (warp & 1) * 64;       // 0,64
    const int mBase = blockIdx.y * 128, nBase = blockIdx.x * 128;
    const bool bnt = flags & 2;

    float acc[2][8][4];
#pragma unroll
    for (int i = 0; i < 2; i++)
#pragma unroll
        for (int j = 0; j < 8; j++)
#pragma unroll
            for (int c = 0; c < 4; c++) acc[i][j][c] = 0.f;

    for (int k0 = 0; k0 < K; k0 += 32) {
        // --- stage A tile [128 m][32 k] -> As[k][m]
#pragma unroll
        for (int r = 0; r < 4; r++) {
            int idx = tid + r * 256;
            int m = idx >> 3;
            int k4 = (idx & 7) * 4;
            float4 v = *(const float4*)(A + (size_t)(mBase + m) * lda + k0 + k4);
            As[k4 + 0][m] = __uint_as_float(f2tf32(v.x));
            As[k4 + 1][m] = __uint_as_float(f2tf32(v.y));
            As[k4 + 2][m] = __uint_as_float(f2tf32(v.z));
            As[k4 + 3][m] = __uint_as_float(f2tf32(v.w));
        }
        // --- stage B tile -> Bs[k][n]
        if (bnt) {
#pragma unroll
            for (int r = 0; r < 4; r++) {
                int idx = tid + r * 256;
                int n = idx >> 3;
                int k4 = (idx & 7) * 4;
                float4 v = make_float4(0.f, 0.f, 0.f, 0.f);
                if (nBase + n < N)
                    v = *(const float4*)(B + (size_t)(nBase + n) * ldb + k0 + k4);
                Bs[k4 + 0][n] = __uint_as_float(f2tf32(v.x));
                Bs[k4 + 1][n] = __uint_as_float(f2tf32(v.y));
                Bs[k4 + 2][n] = __uint_as_float(f2tf32(v.z));
                Bs[k4 + 3][n] = __uint_as_float(f2tf32(v.w));
            }
        } else {
#pragma unroll
            for (int r = 0; r < 4; r++) {
                int idx = tid + r * 256;
                int k = idx >> 5;
                int n4 = (idx & 31) * 4;
                float4 v = make_float4(0.f, 0.f, 0.f, 0.f);
                if (nBase + n4 < N)
                    v = *(const float4*)(B + (size_t)(k0 + k) * ldb + nBase + n4);
                float4 w;
                w.x = __uint_as_float(f2tf32(v.x));
                w.y = __uint_as_float(f2tf32(v.y));
                w.z = __uint_as_float(f2tf32(v.z));
                w.w = __uint_as_float(f2tf32(v.w));
                *(float4*)&Bs[k][n4] = w;
            }
        }
        __syncthreads();

        // --- compute: 4 k8-steps
#pragma unroll
        for (int kk = 0; kk < 4; kk++) {
            const int kb = kk * 8;
            unsigned a[2][4], b[8][2];
#pragma unroll
            for (int mt = 0; mt < 2; mt++) {
                int mr = wm + mt * 16 + g;
                a[mt][0] = __float_as_uint(As[kb + t4    ][mr    ]);
                a[mt][1] = __float_as_uint(As[kb + t4    ][mr + 8]);
                a[mt][2] = __float_as_uint(As[kb + t4 + 4][mr    ]);
                a[mt][3] = __float_as_uint(As[kb + t4 + 4][mr + 8]);
            }
#pragma unroll
            for (int nt = 0; nt < 8; nt++) {
                int nc = wn + nt * 8 + g;
                b[nt][0] = __float_as_uint(Bs[kb + t4    ][nc]);
                b[nt][1] = __float_as_uint(Bs[kb + t4 + 4][nc]);
            }
#pragma unroll
            for (int mt = 0; mt < 2; mt++)
#pragma unroll
                for (int nt = 0; nt < 8; nt++)
                    mma_tf32(acc[mt][nt], a[mt], b[nt]);
        }
        __syncthreads();
    }

    // --- epilogue
    const bool relu = flags & 1;
#pragma unroll
    for (int mt = 0; mt < 2; mt++) {
#pragma unroll
        for (int half = 0; half < 2; half++) {
            int m = mBase + wm + mt * 16 + g + half * 8;
            float i0 = 0.f, i1 = 0.f, i2 = 0.f, i3 = 0.f;
            if (inter4) {
                const float* ip = inter4 + (size_t)m * 4;
                i0 = ip[0]; i1 = ip[1]; i2 = ip[2]; i3 = ip[3];
            }
#pragma unroll
            for (int nt = 0; nt < 8; nt++) {
#pragma unroll
                for (int c = 0; c < 2; c++) {
                    int n = nBase + wn + nt * 8 + 2 * t4 + c;
                    if (n < N) {
                        float v = acc[mt][nt][half * 2 + c];
                        if (bias) v += bias[n];
                        if (res)  v += res[(size_t)m * ldc + n];
                        if (b2) {
                            const float* bp = b2 + (size_t)n * 4;
                            v += i0 * bp[0] + i1 * bp[1] + i2 * bp[2] + i3 * bp[3];
                        }
                        if (relu) v = fmaxf(v, 0.f);
                        C[(size_t)m * ldc + n] = v;
                    }
                }
            }
        }
    }
}

// ---------------- row softmax over 2048 (with 1/sqrt(64) scale) -------------
__global__ void __launch_bounds__(256) softmax_kernel(float* __restrict__ s)
{
    float* row = s + (size_t)blockIdx.x * SS;
    const int tid = threadIdx.x;
    float4 v[2];
    v[0] = ((float4*)row)[tid * 2];
    v[1] = ((float4*)row)[tid * 2 + 1];
    float vals[8] = {v[0].x, v[0].y, v[0].z, v[0].w, v[1].x, v[1].y, v[1].z, v[1].w};
    float mx = -INFINITY;
#pragma unroll
    for (int i = 0; i < 8; i++) {
        vals[i] *= 0.125f;
        mx = fmaxf(mx, vals[i]);
    }
#pragma unroll
    for (int o = 16; o; o >>= 1) mx = fmaxf(mx, __shfl_xor_sync(0xffffffffu, mx, o));
    __shared__ float red[8];
    if ((tid & 31) == 0) red[tid >> 5] = mx;
    __syncthreads();
    mx = red[0];
#pragma unroll
    for (int i = 1; i < 8; i++) mx = fmaxf(mx, red[i]);

    float sum = 0.f;
#pragma unroll
    for (int i = 0; i < 8; i++) {
        vals[i] = __expf(vals[i] - mx);
        sum += vals[i];
    }
#pragma unroll
    for (int o = 16; o; o >>= 1) sum += __shfl_xor_sync(0xffffffffu, sum, o);
    __syncthreads();
    if ((tid & 31) == 0) red[tid >> 5] = sum;
    __syncthreads();
    sum = 0.f;
#pragma unroll
    for (int i = 0; i < 8; i++) sum += red[i];
    float inv = 1.f / sum;
    v[0] = make_float4(vals[0] * inv, vals[1] * inv, vals[2] * inv, vals[3] * inv);
    v[1] = make_float4(vals[4] * inv, vals[5] * inv, vals[6] * inv, vals[7] * inv);
    ((float4*)row)[tid * 2] = v[0];
    ((float4*)row)[tid * 2 + 1] = v[1];
}

// ---------------- small helper kernels -------------------------------------
__global__ void build_WBt(const float* __restrict__ hB_w2,
                          const float* __restrict__ hB_b2,
                          float* __restrict__ WBt)
{
    int idx = blockIdx.x * 256 + threadIdx.x;
    if (idx >= (RR * HID + RR) * EE) return;
    int n = idx / EE, e = idx % EE;
    float val;
    if (n < RR * HID) {
        int r = n >> 7, h = n & 127;
        val = hB_w2[((size_t)(r * EE + e)) * HID + h];
    } else {
        val = hB_b2[(n - RR * HID) * EE + e];
    }
    WBt[idx] = val;
}

__global__ void inter_kernel(const float* __restrict__ v,
                             const float* __restrict__ hB,
                             float* __restrict__ inter)
{
    int warp = (blockIdx.x * blockDim.x + threadIdx.x) >> 5;
    int lane = threadIdx.x & 31;
    if (warp >= MM) return;
    const float* vr = v + (size_t)warp * (RR * HID + RR);
    const float* br = hB + (size_t)warp * HID;
#pragma unroll
    for (int r = 0; r < RR; r++) {
        float s = 0.f;
#pragma unroll
        for (int j = 0; j < 4; j++) {
            int hh = lane + j * 32;
            s += br[hh] * vr[r * HID + hh];
        }
#pragma unroll
        for (int o = 16; o; o >>= 1) s += __shfl_down_sync(0xffffffffu, s, o);
        if (lane == 0) inter[warp * RR + r] = s + vr[RR * HID + r];
    }
}

__global__ void u_kernel(const float* __restrict__ inter,
                         const float* __restrict__ hA,
                         float* __restrict__ u)
{
    int idx = blockIdx.x * 256 + threadIdx.x;
    if (idx >= MM * RR * HID) return;
    int m = idx >> 9;
    int c = idx & 511;
    int r = c >> 7;
    u[idx] = inter[m * RR + r] * hA[m * HID + (c & 127)];
}

// ---------------- launch ----------------------------------------------------
extern "C" void kernel_launch(void* const* d_in, const int* in_sizes, int n_in,
                              void* d_out, int out_size)
{
    const float* src       = (const float*)d_in[0];
    const float* task      = (const float*)d_in[1];
    const float* norm1_w   = (const float*)d_in[2];
    const float* norm2_w   = (const float*)d_in[3];
    const float* in_proj_w = (const float*)d_in[4];
    const float* out_proj_w= (const float*)d_in[5];
    const float* ffn1_w    = (const float*)d_in[6];
    const float* ffn1_b    = (const float*)d_in[7];
    const float* ffn2_w    = (const float*)d_in[8];
    const float* ffn2_b    = (const float*)d_in[9];
    const float* hA_w1     = (const float*)d_in[10];
    const float* hA_b1     = (const float*)d_in[11];
    const float* hA_w2     = (const float*)d_in[12];
    const float* hA_b2     = (const float*)d_in[13];
    const float* hB_w1     = (const float*)d_in[14];
    const float* hB_b1     = (const float*)d_in[15];
    const float* hB_w2     = (const float*)d_in[16];
    const float* hB_b2     = (const float*)d_in[17];
    float* out = (float*)d_out;

    float *x1, *qkv, *ctx, *src2, *x2, *hA, *hB, *WBt, *v, *inter, *u, *hbuf, *scores;
    cudaGetSymbolAddress((void**)&x1,   g_x1);
    cudaGetSymbolAddress((void**)&qkv,  g_qkv);
    cudaGetSymbolAddress((void**)&ctx,  g_ctx);
    cudaGetSymbolAddress((void**)&src2, g_src2);
    cudaGetSymbolAddress((void**)&x2,   g_x2);
    cudaGetSymbolAddress((void**)&hA,   g_hA);
    cudaGetSymbolAddress((void**)&hB,   g_hB);
    cudaGetSymbolAddress((void**)&WBt,  g_WBt);
    cudaGetSymbolAddress((void**)&v,    g_v);
    cudaGetSymbolAddress((void**)&inter,g_int);
    cudaGetSymbolAddress((void**)&u,    g_u);
    cudaGetSymbolAddress((void**)&hbuf, g_h);
    cudaGetSymbolAddress((void**)&scores, g_scores);

    const long long ZS = (long long)SS * SS;

    // 1) x1 = rmsnorm(src, norm1_w)
    rmsnorm_kernel<<<MM, 256>>>(src, norm1_w, x1);

    // 2) qkv = x1 @ in_proj_w^T   [4096, 2304]
    mma_gemm<<<dim3(18, 32, 1), 256>>>(
        x1, in_proj_w, qkv, nullptr, nullptr, nullptr, nullptr,
        MM, 3 * EE, EE, EE, EE, 3 * EE, 0, 0, 0, 0, 0, 0, 2);

    // 3a) scores[z] = Q @ K^T  (batched over z = b*12+h)
    mma_gemm<<<dim3(16, 16, BB * HH), 256>>>(
        qkv, qkv + EE, scores, nullptr, nullptr, nullptr, nullptr,
        SS, SS, HD, 3 * EE, 3 * EE, SS,
        (long long)SS * 3 * EE, HD, (long long)SS * 3 * EE, HD,
        (long long)HH * ZS, ZS, 2);

    // 3b) softmax rows
    softmax_kernel<<<BB * HH * SS, 256>>>(scores);

    // 3c) ctx[z] = P @ V (nn)
    mma_gemm<<<dim3(1, 16, BB * HH), 256>>>(
        scores, qkv + 2 * EE, ctx, nullptr, nullptr, nullptr, nullptr,
        SS, HD, SS, SS, 3 * EE, EE,
        (long long)HH * ZS, ZS, (long long)SS * 3 * EE, HD,
        (long long)SS * EE, HD, 0);

    // 4) src2 = src + ctx @ out_proj_w^T
    mma_gemm<<<dim3(6, 32, 1), 256>>>(
        ctx, out_proj_w, src2, nullptr, src, nullptr, nullptr,
        MM, EE, EE, EE, EE, EE, 0, 0, 0, 0, 0, 0, 2);

    // 5) x2 = rmsnorm(src2, norm2_w)
    rmsnorm_kernel<<<MM, 256>>>(src2, norm2_w, x2);

    // 6) hypernet hiddens
    mma_gemm<<<dim3(1, 32, 1), 256>>>(
        task, hA_w1, hA, hA_b1, nullptr, nullptr, nullptr,
        MM, HID, TT, TT, TT, HID, 0, 0, 0, 0, 0, 0, 3);
    mma_gemm<<<dim3(1, 32, 1), 256>>>(
        task, hB_w1, hB, hB_b1, nullptr, nullptr, nullptr,
        MM, HID, TT, TT, TT, HID, 0, 0, 0, 0, 0, 0, 3);

    // 7) rearrange B-side weights
    build_WBt<<<((RR * HID + RR) * EE + 255) / 256, 256>>>(hB_w2, hB_b2, WBt);

    // 8) v = x2 @ WBt^T  [4096, 516]
    mma_gemm<<<dim3(5, 32, 1), 256>>>(
        x2, WBt, v, nullptr, nullptr, nullptr, nullptr,
        MM, RR * HID + RR, EE, EE, EE, RR * HID + RR, 0, 0, 0, 0, 0, 0, 2);

    // 9) inter[m,r]
    inter_kernel<<<(MM * 32 + 255) / 256, 256>>>(v, hB, inter);

    // 10) u = inter x hA outer product  [4096,512]
    u_kernel<<<(MM * RR * HID + 255) / 256, 256>>>(inter, hA, u);

    // 11) base = x2 @ ffn1_w^T + ffn1_b -> hbuf
    mma_gemm<<<dim3(24, 32, 1), 256>>>(
        x2, ffn1_w, hbuf, ffn1_b, nullptr, nullptr, nullptr,
        MM, FF, EE, EE, EE, FF, 0, 0, 0, 0, 0, 0, 2);

    // 12) hbuf = relu(hbuf + u @ hA_w2^T + lora bias term)
    mma_gemm<<<dim3(24, 32, 1), 256>>>(
        u, hA_w2, hbuf, nullptr, hbuf, inter, hA_b2,
        MM, FF, RR * HID, RR * HID, RR * HID, FF, 0, 0, 0, 0, 0, 0, 3);

    // 13) out = src2 + hbuf @ ffn2_w^T + ffn2_b
    mma_gemm<<<dim3(6, 32, 1), 256>>>(
        hbuf, ffn2_w, out, ffn2_b, src2, nullptr, nullptr,
        MM, EE, FF, FF, FF, EE, 0, 0, 0, 0, 0, 0, 2);
}

// round 3
// speedup vs baseline: 2.1834x; 1.2033x over previous
#include <cuda_runtime.h>
#include <cuda_bf16.h>
#include <math.h>

// Problem constants
#define BB 2
#define SS 2048
#define EE 768
#define FF 3072
#define RR 4
#define TT 128
#define HH 12
#define HD 64
#define HID 128
#define MM (BB*SS)          // 4096 tokens

// ---------------- scratch (device globals; no cudaMalloc allowed) ----------
__device__ float g_x1  [MM*EE];
__device__ float g_qkv [MM*3*EE];
__device__ float g_ctx [MM*EE];
__device__ float g_src2[MM*EE];
__device__ float g_x2  [MM*EE];
__device__ float g_hA  [MM*HID];
__device__ float g_hB  [MM*HID];
__device__ float g_WBt [(RR*HID+RR)*EE];
__device__ float g_v   [MM*(RR*HID+RR)];
__device__ float g_int [MM*RR];
__device__ float g_u   [MM*RR*HID];
__device__ float g_h   [MM*FF];

// ---------------- helpers ---------------------------------------------------
__device__ __forceinline__ unsigned f2tf32(float f) {
    unsigned u;
    asm("cvt.rna.tf32.f32 %0, %1;" : "=r"(u) : "f"(f));
    return u;
}

__device__ __forceinline__ void mma_tf32(float c[4], const unsigned a[4], const unsigned b[2]) {
    asm volatile(
        "mma.sync.aligned.m16n8k8.row.col.f32.tf32.tf32.f32 "
        "{%0,%1,%2,%3}, {%4,%5,%6,%7}, {%8,%9}, {%0,%1,%2,%3};\n"
        : "+f"(c[0]), "+f"(c[1]), "+f"(c[2]), "+f"(c[3])
        : "r"(a[0]), "r"(a[1]), "r"(a[2]), "r"(a[3]), "r"(b[0]), "r"(b[1]));
}

// ---------------- rmsnorm --------------------------------------------------
__global__ void __launch_bounds__(256) rmsnorm_kernel(
    const float* __restrict__ x, const float* __restrict__ w, float* __restrict__ y)
{
    int row = blockIdx.x;
    const float* xr = x + (size_t)row * EE;
    float vals[3];
    float s = 0.f;
#pragma unroll
    for (int i = 0; i < 3; i++) {
        vals[i] = xr[threadIdx.x + i * 256];
        s += vals[i] * vals[i];
    }
#pragma unroll
    for (int o = 16; o; o >>= 1) s += __shfl_down_sync(0xffffffffu, s, o);
    __shared__ float red[8];
    if ((threadIdx.x & 31) == 0) red[threadIdx.x >> 5] = s;
    __syncthreads();
    if (threadIdx.x < 8) {
        float t = red[threadIdx.x];
#pragma unroll
        for (int o = 4; o; o >>= 1) t += __shfl_down_sync(0xffu, t, o);
        if (threadIdx.x == 0) red[0] = t;
    }
    __syncthreads();
    float r = rsqrtf(red[0] * (1.0f / EE) + 1.1920929e-7f);
    float* yr = y + (size_t)row * EE;
#pragma unroll
    for (int i = 0; i < 3; i++) {
        int c = threadIdx.x + i * 256;
        yr[c] = vals[i] * r * w[c];
    }
}

// ---------------- tf32 tensor-core GEMM, double-buffered --------------------
// C = A @ W^T (+epilogues). A:[M,K] rm, W:[N,K] rm, C:[M,N]
// flags bit0: relu
#define ASM(buf,k,m) dyn[((buf)*32+(k))*132 + (m)]
#define BSM(buf,k,n) dyn[8448 + ((buf)*32+(k))*132 + (n)]

__global__ void __launch_bounds__(256) mma_gemm(
    const float* __restrict__ A, const float* __restrict__ B, float* __restrict__ C,
    const float* __restrict__ bias, const float* __restrict__ res,
    const float* __restrict__ inter4, const float* __restrict__ b2,
    int M, int N, int K, int lda, int ldb, int ldc, int flags)
{
    extern __shared__ float dyn[];
    const int tid  = threadIdx.x;
    const int lane = tid & 31, warp = tid >> 5;
    const int g = lane >> 2, t4 = lane & 3;
    const int wm = (warp >> 1) * 32;
    const int wn = (warp & 1) * 64;
    const int mBase = blockIdx.y * 128, nBase = blockIdx.x * 128;
    const int lr = tid >> 3;            // 0..31
    const int kA = (tid & 7) * 4;       // 0,4,..,28

    float acc[2][8][4];
#pragma unroll
    for (int i = 0; i < 2; i++)
#pragma unroll
        for (int j = 0; j < 8; j++)
#pragma unroll
            for (int c = 0; c < 4; c++) acc[i][j][c] = 0.f;

    float4 ra[4], rb[4];
    const int nIter = K >> 5;

    // prologue: tile 0
#pragma unroll
    for (int r = 0; r < 4; r++) {
        int row = lr + r * 32;
        ra[r] = *(const float4*)(A + (size_t)(mBase + row) * lda + kA);
        rb[r] = make_float4(0.f, 0.f, 0.f, 0.f);
        if (nBase + row < N)
            rb[r] = *(const float4*)(B + (size_t)(nBase + row) * ldb + kA);
    }
#pragma unroll
    for (int r = 0; r < 4; r++) {
        int row = lr + r * 32;
        ASM(0, kA + 0, row) = __uint_as_float(f2tf32(ra[r].x));
        ASM(0, kA + 1, row) = __uint_as_float(f2tf32(ra[r].y));
        ASM(0, kA + 2, row) = __uint_as_float(f2tf32(ra[r].z));
        ASM(0, kA + 3, row) = __uint_as_float(f2tf32(ra[r].w));
        BSM(0, kA + 0, row) = __uint_as_float(f2tf32(rb[r].x));
        BSM(0, kA + 1, row) = __uint_as_float(f2tf32(rb[r].y));
        BSM(0, kA + 2, row) = __uint_as_float(f2tf32(rb[r].z));
        BSM(0, kA + 3, row) = __uint_as_float(f2tf32(rb[r].w));
    }
    __syncthreads();

    for (int it = 0; it < nIter; it++) {
        const int buf = it & 1;
        // prefetch next tile into regs
        if (it + 1 < nIter) {
            int k0 = (it + 1) * 32;
#pragma unroll
            for (int r = 0; r < 4; r++) {
                int row = lr + r * 32;
                ra[r] = *(const float4*)(A + (size_t)(mBase + row) * lda + k0 + kA);
                rb[r] = make_float4(0.f, 0.f, 0.f, 0.f);
                if (nBase + row < N)
                    rb[r] = *(const float4*)(B + (size_t)(nBase + row) * ldb + k0 + kA);
            }
        }
        // compute current tile
#pragma unroll
        for (int kk = 0; kk < 4; kk++) {
            const int kb = kk * 8;
            unsigned a[2][4], b[8][2];
#pragma unroll
            for (int mt = 0; mt < 2; mt++) {
                int mr = wm + mt * 16 + g;
                a[mt][0] = __float_as_uint(ASM(buf, kb + t4,     mr));
                a[mt][1] = __float_as_uint(ASM(buf, kb + t4,     mr + 8));
                a[mt][2] = __float_as_uint(ASM(buf, kb + t4 + 4, mr));
                a[mt][3] = __float_as_uint(ASM(buf, kb + t4 + 4, mr + 8));
            }
#pragma unroll
            for (int nt = 0; nt < 8; nt++) {
                int nc = wn + nt * 8 + g;
                b[nt][0] = __float_as_uint(BSM(buf, kb + t4,     nc));
                b[nt][1] = __float_as_uint(BSM(buf, kb + t4 + 4, nc));
            }
#pragma unroll
            for (int mt = 0; mt < 2; mt++)
#pragma unroll
                for (int nt = 0; nt < 8; nt++)
                    mma_tf32(acc[mt][nt], a[mt], b[nt]);
        }
        // store prefetched tile into other buffer
        if (it + 1 < nIter) {
            const int nb = buf ^ 1;
#pragma unroll
            for (int r = 0; r < 4; r++) {
                int row = lr + r * 32;
                ASM(nb, kA + 0, row) = __uint_as_float(f2tf32(ra[r].x));
                ASM(nb, kA + 1, row) = __uint_as_float(f2tf32(ra[r].y));
                ASM(nb, kA + 2, row) = __uint_as_float(f2tf32(ra[r].z));
                ASM(nb, kA + 3, row) = __uint_as_float(f2tf32(ra[r].w));
                BSM(nb, kA + 0, row) = __uint_as_float(f2tf32(rb[r].x));
                BSM(nb, kA + 1, row) = __uint_as_float(f2tf32(rb[r].y));
                BSM(nb, kA + 2, row) = __uint_as_float(f2tf32(rb[r].z));
                BSM(nb, kA + 3, row) = __uint_as_float(f2tf32(rb[r].w));
            }
            __syncthreads();
        }
    }

    // --- epilogue
    const bool relu = flags & 1;
#pragma unroll
    for (int mt = 0; mt < 2; mt++) {
#pragma unroll
        for (int half = 0; half < 2; half++) {
            int m = mBase + wm + mt * 16 + g + half * 8;
            float i0 = 0.f, i1 = 0.f, i2 = 0.f, i3 = 0.f;
            if (inter4) {
                const float* ip = inter4 + (size_t)m * 4;
                i0 = ip[0]; i1 = ip[1]; i2 = ip[2]; i3 = ip[3];
            }
#pragma unroll
            for (int nt = 0; nt < 8; nt++) {
#pragma unroll
                for (int c = 0; c < 2; c++) {
                    int n = nBase + wn + nt * 8 + 2 * t4 + c;
                    if (n < N) {
                        float v = acc[mt][nt][half * 2 + c];
                        if (bias) v += bias[n];
                        if (res)  v += res[(size_t)m * ldc + n];
                        if (b2) {
                            const float* bp = b2 + (size_t)n * 4;
                            v += i0 * bp[0] + i1 * bp[1] + i2 * bp[2] + i3 * bp[3];
                        }
                        if (relu) v = fmaxf(v, 0.f);
                        C[(size_t)m * ldc + n] = v;
                    }
                }
            }
        }
    }
}

// ---------------- flash attention -------------------------------------------
// grid: (SS/128, BB*HH). block 256 = 8 warps, each warp owns 16 query rows.
#define QP 68
#define VP 72
__global__ void __launch_bounds__(256) flash_attn(
    const float* __restrict__ qkv, float* __restrict__ ctx)
{
    __shared__ float pool[64 * QP + 64 * VP];
    float* Ks = pool;
    float* Vs = pool + 64 * QP;

    const int z = blockIdx.y, b = z / HH, h = z % HH;
    const float* base = qkv + (size_t)b * SS * 3 * EE + h * HD;
    const int q0 = blockIdx.x * 128;
    const int tid = threadIdx.x, lane = tid & 31, warp = tid >> 5;
    const int g = lane >> 2, t4 = lane & 3;
    const float qscale = 0.125f * 1.4426950408889634f;  // 1/sqrt(64) * log2(e)

    // ---- stage Q (scaled, tf32) through smem, then load register fragments
#pragma unroll
    for (int r = 0; r < 8; r++) {
        int idx = tid + r * 256;           // 0..2047
        int row = idx >> 4, c4 = (idx & 15) * 4;
        float4 v = *(const float4*)(base + (size_t)(q0 + row) * 3 * EE + c4);
        float4 w;
        w.x = __uint_as_float(f2tf32(v.x * qscale));
        w.y = __uint_as_float(f2tf32(v.y * qscale));
        w.z = __uint_as_float(f2tf32(v.z * qscale));
        w.w = __uint_as_float(f2tf32(v.w * qscale));
        *(float4*)(pool + row * QP + c4) = w;
    }
    __syncthreads();
    unsigned qf[8][4];
    const int wq = warp * 16;
#pragma unroll
    for (int kc = 0; kc < 8; kc++) {
        qf[kc][0] = __float_as_uint(pool[(wq + g)     * QP + kc * 8 + t4]);
        qf[kc][1] = __float_as_uint(pool[(wq + g + 8) * QP + kc * 8 + t4]);
        qf[kc][2] = __float_as_uint(pool[(wq + g)     * QP + kc * 8 + t4 + 4]);
        qf[kc][3] = __float_as_uint(pool[(wq + g + 8) * QP + kc * 8 + t4 + 4]);
    }
    __syncthreads();

    float o[8][4];
#pragma unroll
    for (int v = 0; v < 8; v++)
#pragma unroll
        for (int c = 0; c < 4; c++) o[v][c] = 0.f;
    float m0 = -INFINITY, m1 = -INFINITY, l0 = 0.f, l1 = 0.f;

    const int Le = (lane & 28) | (t4 >> 1);
    const int Lo = Le | 2;
    const bool odd = t4 & 1;

    for (int kt = 0; kt < SS / 64; kt++) {
        // ---- load K/V tiles (64 keys x 64), tf32
#pragma unroll
        for (int r = 0; r < 4; r++) {
            int idx = tid + r * 256;       // 0..1023
            int row = idx >> 4, c4 = (idx & 15) * 4;
            const float* kp = base + EE     + (size_t)(kt * 64 + row) * 3 * EE + c4;
            const float* vp = base + 2 * EE + (size_t)(kt * 64 + row) * 3 * EE + c4;
            float4 kv = *(const float4*)kp;
            float4 vv = *(const float4*)vp;
            float4 kw, vw;
            kw.x = __uint_as_float(f2tf32(kv.x)); kw.y = __uint_as_float(f2tf32(kv.y));
            kw.z = __uint_as_float(f2tf32(kv.z)); kw.w = __uint_as_float(f2tf32(kv.w));
            vw.x = __uint_as_float(f2tf32(vv.x)); vw.y = __uint_as_float(f2tf32(vv.y));
            vw.z = __uint_as_float(f2tf32(vv.z)); vw.w = __uint_as_float(f2tf32(vv.w));
            *(float4*)(Ks + row * QP + c4) = kw;
            *(float4*)(Vs + row * VP + c4) = vw;
        }
        __syncthreads();

        // ---- scores: s[j] = Q(16xHD) . K^T  (64 keys as 8 n-tiles)
        float s[8][4];
#pragma unroll
        for (int j = 0; j < 8; j++)
#pragma unroll
            for (int c = 0; c < 4; c++) s[j][c] = 0.f;
#pragma unroll
        for (int j = 0; j < 8; j++) {
#pragma unroll
            for (int kc = 0; kc < 8; kc++) {
                unsigned bfr[2];
                bfr[0] = __float_as_uint(Ks[(j * 8 + g) * QP + kc * 8 + t4]);
                bfr[1] = __float_as_uint(Ks[(j * 8 + g) * QP + kc * 8 + t4 + 4]);
                mma_tf32(s[j], qf[kc], bfr);
            }
        }

        // ---- online softmax (log2 domain; scale folded into Q)
        float r0 = -INFINITY, r1 = -INFINITY;
#pragma unroll
        for (int j = 0; j < 8; j++) {
            r0 = fmaxf(r0, fmaxf(s[j][0], s[j][1]));
            r1 = fmaxf(r1, fmaxf(s[j][2], s[j][3]));
        }
        r0 = fmaxf(r0, __shfl_xor_sync(0xffffffffu, r0, 1));
        r0 = fmaxf(r0, __shfl_xor_sync(0xffffffffu, r0, 2));
        r1 = fmaxf(r1, __shfl_xor_sync(0xffffffffu, r1, 1));
        r1 = fmaxf(r1, __shfl_xor_sync(0xffffffffu, r1, 2));
        float m0n = fmaxf(m0, r0), m1n = fmaxf(m1, r1);
        float c0 = exp2f(m0 - m0n), c1 = exp2f(m1 - m1n);
        l0 *= c0; l1 *= c1;
#pragma unroll
        for (int v = 0; v < 8; v++) {
            o[v][0] *= c0; o[v][1] *= c0;
            o[v][2] *= c1; o[v][3] *= c1;
        }
        m0 = m0n; m1 = m1n;
#pragma unroll
        for (int j = 0; j < 8; j++) {
            s[j][0] = exp2f(s[j][0] - m0);
            s[j][1] = exp2f(s[j][1] - m0);
            s[j][2] = exp2f(s[j][2] - m1);
            s[j][3] = exp2f(s[j][3] - m1);
            l0 += s[j][0] + s[j][1];
            l1 += s[j][2] + s[j][3];
        }

        // ---- P.V: convert C-frag -> A-frag via shuffles, then mma
#pragma unroll
        for (int j = 0; j < 8; j++) {
            float e0 = __shfl_sync(0xffffffffu, s[j][0], Le);
            float f0 = __shfl_sync(0xffffffffu, s[j][1], Le);
            float e1 = __shfl_sync(0xffffffffu, s[j][2], Le);
            float f1 = __shfl_sync(0xffffffffu, s[j][3], Le);
            float e2 = __shfl_sync(0xffffffffu, s[j][0], Lo);
            float f2 = __shfl_sync(0xffffffffu, s[j][1], Lo);
            float e3 = __shfl_sync(0xffffffffu, s[j][2], Lo);
            float f3 = __shfl_sync(0xffffffffu, s[j][3], Lo);
            unsigned pa[4];
            pa[0] = f2tf32(odd ? f0 : e0);
            pa[1] = f2tf32(odd ? f1 : e1);
            pa[2] = f2tf32(odd ? f2 : e2);
            pa[3] = f2tf32(odd ? f3 : e3);
#pragma unroll
            for (int v = 0; v < 8; v++) {
                unsigned bfr[2];
                bfr[0] = __float_as_uint(Vs[(j * 8 + t4)     * VP + v * 8 + g]);
                bfr[1] = __float_as_uint(Vs[(j * 8 + t4 + 4) * VP + v * 8 + g]);
                mma_tf32(o[v], pa, bfr);
            }
        }
        __syncthreads();
    }

    // ---- finalize
    l0 += __shfl_xor_sync(0xffffffffu, l0, 1);
    l0 += __shfl_xor_sync(0xffffffffu, l0, 2);
    l1 += __shfl_xor_sync(0xffffffffu, l1, 1);
    l1 += __shfl_xor_sync(0xffffffffu, l1, 2);
    float inv0 = 1.f / l0, inv1 = 1.f / l1;
    int row0 = q0 + wq + g, row1 = row0 + 8;
    float* c0p = ctx + ((size_t)(b * SS + row0)) * EE + h * HD;
    float* c1p = ctx + ((size_t)(b * SS + row1)) * EE + h * HD;
#pragma unroll
    for (int v = 0; v < 8; v++) {
        int col = v * 8 + 2 * t4;
        float2 w0 = make_float2(o[v][0] * inv0, o[v][1] * inv0);
        float2 w1 = make_float2(o[v][2] * inv1, o[v][3] * inv1);
        *(float2*)(c0p + col) = w0;
        *(float2*)(c1p + col) = w1;
    }
}

// ---------------- small helper kernels -------------------------------------
__global__ void build_WBt(const float* __restrict__ hB_w2,
                          const float* __restrict__ hB_b2,
                          float* __restrict__ WBt)
{
    int idx = blockIdx.x * 256 + threadIdx.x;
    if (idx >= (RR * HID + RR) * EE) return;
    int n = idx / EE, e = idx % EE;
    float val;
    if (n < RR * HID) {
        int r = n >> 7, h = n & 127;
        val = hB_w2[((size_t)(r * EE + e)) * HID + h];
    } else {
        val = hB_b2[(n - RR * HID) * EE + e];
    }
    WBt[idx] = val;
}

__global__ void inter_kernel(const float* __restrict__ v,
                             const float* __restrict__ hB,
                             float* __restrict__ inter)
{
    int warp = (blockIdx.x * blockDim.x + threadIdx.x) >> 5;
    int lane = threadIdx.x & 31;
    if (warp >= MM) return;
    const float* vr = v + (size_t)warp * (RR * HID + RR);
    const float* br = hB + (size_t)warp * HID;
#pragma unroll
    for (int r = 0; r < RR; r++) {
        float s = 0.f;
#pragma unroll
        for (int j = 0; j < 4; j++) {
            int hh = lane + j * 32;
            s += br[hh] * vr[r * HID + hh];
        }
#pragma unroll
        for (int o = 16; o; o >>= 1) s += __shfl_down_sync(0xffffffffu, s, o);
        if (lane == 0) inter[warp * RR + r] = s + vr[RR * HID + r];
    }
}

__global__ void u_kernel(const float* __restrict__ inter,
                         const float* __restrict__ hA,
                         float* __restrict__ u)
{
    int idx = blockIdx.x * 256 + threadIdx.x;
    if (idx >= MM * RR * HID) return;
    int m = idx >> 9;
    int c = idx & 511;
    int r = c >> 7;
    u[idx] = inter[m * RR + r] * hA[m * HID + (c & 127)];
}

// ---------------- launch ----------------------------------------------------
extern "C" void kernel_launch(void* const* d_in, const int* in_sizes, int n_in,
                              void* d_out, int out_size)
{
    const float* src       = (const float*)d_in[0];
    const float* task      = (const float*)d_in[1];
    const float* norm1_w   = (const float*)d_in[2];
    const float* norm2_w   = (const float*)d_in[3];
    const float* in_proj_w = (const float*)d_in[4];
    const float* out_proj_w= (const float*)d_in[5];
    const float* ffn1_w    = (const float*)d_in[6];
    const float* ffn1_b    = (const float*)d_in[7];
    const float* ffn2_w    = (const float*)d_in[8];
    const float* ffn2_b    = (const float*)d_in[9];
    const float* hA_w1     = (const float*)d_in[10];
    const float* hA_b1     = (const float*)d_in[11];
    const float* hA_w2     = (const float*)d_in[12];
    const float* hA_b2     = (const float*)d_in[13];
    const float* hB_w1     = (const float*)d_in[14];
    const float* hB_b1     = (const float*)d_in[15];
    const float* hB_w2     = (const float*)d_in[16];
    const float* hB_b2     = (const float*)d_in[17];
    float* out = (float*)d_out;

    float *x1, *qkv, *ctx, *src2, *x2, *hA, *hB, *WBt, *v, *inter, *u, *hbuf;
    cudaGetSymbolAddress((void**)&x1,   g_x1);
    cudaGetSymbolAddress((void**)&qkv,  g_qkv);
    cudaGetSymbolAddress((void**)&ctx,  g_ctx);
    cudaGetSymbolAddress((void**)&src2, g_src2);
    cudaGetSymbolAddress((void**)&x2,   g_x2);
    cudaGetSymbolAddress((void**)&hA,   g_hA);
    cudaGetSymbolAddress((void**)&hB,   g_hB);
    cudaGetSymbolAddress((void**)&WBt,  g_WBt);
    cudaGetSymbolAddress((void**)&v,    g_v);
    cudaGetSymbolAddress((void**)&inter,g_int);
    cudaGetSymbolAddress((void**)&u,    g_u);
    cudaGetSymbolAddress((void**)&hbuf, g_h);

    const int DS = 2 * 2 * 32 * 132 * 4;  // 67584 B dynamic smem
    cudaFuncSetAttribute(mma_gemm, cudaFuncAttributeMaxDynamicSharedMemorySize, DS);

    // 1) x1 = rmsnorm(src, norm1_w)
    rmsnorm_kernel<<<MM, 256>>>(src, norm1_w, x1);

    // 2) qkv = x1 @ in_proj_w^T   [4096, 2304]
    mma_gemm<<<dim3(18, 32), 256, DS>>>(
        x1, in_proj_w, qkv, nullptr, nullptr, nullptr, nullptr,
        MM, 3 * EE, EE, EE, EE, 3 * EE, 0);

    // 3) flash attention -> ctx
    flash_attn<<<dim3(SS / 128, BB * HH), 256>>>(qkv, ctx);

    // 4) src2 = src + ctx @ out_proj_w^T
    mma_gemm<<<dim3(6, 32), 256, DS>>>(
        ctx, out_proj_w, src2, nullptr, src, nullptr, nullptr,
        MM, EE, EE, EE, EE, EE, 0);

    // 5) x2 = rmsnorm(src2, norm2_w)
    rmsnorm_kernel<<<MM, 256>>>(src2, norm2_w, x2);

    // 6) hypernet hiddens
    mma_gemm<<<dim3(1, 32), 256, DS>>>(
        task, hA_w1, hA, hA_b1, nullptr, nullptr, nullptr,
        MM, HID, TT, TT, TT, HID, 1);
    mma_gemm<<<dim3(1, 32), 256, DS>>>(
        task, hB_w1, hB, hB_b1, nullptr, nullptr, nullptr,
        MM, HID, TT, TT, TT, HID, 1);

    // 7) rearrange B-side weights
    build_WBt<<<((RR * HID + RR) * EE + 255) / 256, 256>>>(hB_w2, hB_b2, WBt);

    // 8) v = x2 @ WBt^T  [4096, 516]
    mma_gemm<<<dim3(5, 32), 256, DS>>>(
        x2, WBt, v, nullptr, nullptr, nullptr, nullptr,
        MM, RR * HID + RR, EE, EE, EE, RR * HID + RR, 0);

    // 9) inter[m,r]
    inter_kernel<<<(MM * 32 + 255) / 256, 256>>>(v, hB, inter);

    // 10) u = inter x hA outer product  [4096,512]
    u_kernel<<<(MM * RR * HID + 255) / 256, 256>>>(inter, hA, u);

    // 11) base = x2 @ ffn1_w^T + ffn1_b -> hbuf
    mma_gemm<<<dim3(24, 32), 256, DS>>>(
        x2, ffn1_w, hbuf, ffn1_b, nullptr, nullptr, nullptr,
        MM, FF, EE, EE, EE, FF, 0);

    // 12) hbuf = relu(hbuf + u @ hA_w2^T + lora bias term)
    mma_gemm<<<dim3(24, 32), 256, DS>>>(
        u, hA_w2, hbuf, nullptr, hbuf, inter, hA_b2,
        MM, FF, RR * HID, RR * HID, RR * HID, FF, 1);

    // 13) out = src2 + hbuf @ ffn2_w^T + ffn2_b
    mma_gemm<<<dim3(6, 32), 256, DS>>>(
        hbuf, ffn2_w, out, ffn2_b, src2, nullptr, nullptr,
        MM, EE, FF, FF, FF, EE, 0);
}

// round 4
// speedup vs baseline: 2.3433x; 1.0732x over previous
#include <cuda_runtime.h>
#include <cuda_bf16.h>
#include <math.h>

// Problem constants
#define BB 2
#define SS 2048
#define EE 768
#define FF 3072
#define RR 4
#define TT 128
#define HH 12
#define HD 64
#define HID 128
#define MM (BB*SS)          // 4096 tokens

// ---------------- scratch (device globals; no cudaMalloc allowed) ----------
__device__ float g_x1  [MM*EE];
__device__ float g_qkv [MM*3*EE];
__device__ float g_ctx [MM*EE];
__device__ float g_src2[MM*EE];
__device__ float g_x2  [MM*EE];
__device__ float g_hA  [MM*HID];
__device__ float g_hB  [MM*HID];
__device__ float g_WBt [(RR*HID+RR)*EE];
__device__ float g_v   [MM*(RR*HID+RR)];
__device__ float g_int [MM*RR];
__device__ float g_u   [MM*RR*HID];
__device__ float g_h   [MM*FF];
// rounded copies of GEMM operands
__device__ float g_r_task  [MM*TT];
__device__ float g_r_inproj[3*EE*EE];
__device__ float g_r_outproj[EE*EE];
__device__ float g_r_ffn1  [FF*EE];
__device__ float g_r_ffn2  [EE*FF];
__device__ float g_r_hAw2  [FF*RR*HID];
__device__ float g_r_hw1   [2*HID*TT];

// ---------------- helpers ---------------------------------------------------
__device__ __forceinline__ unsigned f2tf32(float f) {
    unsigned u;
    asm("cvt.rna.tf32.f32 %0, %1;" : "=r"(u) : "f"(f));
    return u;
}
__device__ __forceinline__ float rnd(float f) { return __uint_as_float(f2tf32(f)); }

__device__ __forceinline__ void mma_tf32(float c[4], const unsigned a[4], const unsigned b[2]) {
    asm volatile(
        "mma.sync.aligned.m16n8k8.row.col.f32.tf32.tf32.f32 "
        "{%0,%1,%2,%3}, {%4,%5,%6,%7}, {%8,%9}, {%0,%1,%2,%3};\n"
        : "+f"(c[0]), "+f"(c[1]), "+f"(c[2]), "+f"(c[3])
        : "r"(a[0]), "r"(a[1]), "r"(a[2]), "r"(a[3]), "r"(b[0]), "r"(b[1]));
}

__device__ __forceinline__ void cp16(unsigned dst, const float* src) {
    asm volatile("cp.async.cg.shared.global [%0], [%1], 16;\n" :: "r"(dst), "l"(src));
}
__device__ __forceinline__ void cp16z(unsigned dst, const float* src, int sz) {
    asm volatile("cp.async.cg.shared.global [%0], [%1], 16, %2;\n" :: "r"(dst), "l"(src), "r"(sz));
}
__device__ __forceinline__ void cp_commit() { asm volatile("cp.async.commit_group;\n"); }
__device__ __forceinline__ void cp_wait0()  { asm volatile("cp.async.wait_group 0;\n"); }

// ---------------- rounding pass ---------------------------------------------
__global__ void __launch_bounds__(256) round_tf32(
    const float* __restrict__ in, float* __restrict__ out, int n4)
{
    int i = blockIdx.x * 256 + threadIdx.x;
    if (i < n4) {
        float4 v = ((const float4*)in)[i];
        v.x = rnd(v.x); v.y = rnd(v.y); v.z = rnd(v.z); v.w = rnd(v.w);
        ((float4*)out)[i] = v;
    }
}

// ---------------- rmsnorm (output rounded to tf32) --------------------------
__global__ void __launch_bounds__(256) rmsnorm_kernel(
    const float* __restrict__ x, const float* __restrict__ w, float* __restrict__ y)
{
    int row = blockIdx.x;
    const float* xr = x + (size_t)row * EE;
    float vals[3];
    float s = 0.f;
#pragma unroll
    for (int i = 0; i < 3; i++) {
        vals[i] = xr[threadIdx.x + i * 256];
        s += vals[i] * vals[i];
    }
#pragma unroll
    for (int o = 16; o; o >>= 1) s += __shfl_down_sync(0xffffffffu, s, o);
    __shared__ float red[8];
    if ((threadIdx.x & 31) == 0) red[threadIdx.x >> 5] = s;
    __syncthreads();
    if (threadIdx.x < 8) {
        float t = red[threadIdx.x];
#pragma unroll
        for (int o = 4; o; o >>= 1) t += __shfl_down_sync(0xffu, t, o);
        if (threadIdx.x == 0) red[0] = t;
    }
    __syncthreads();
    float r = rsqrtf(red[0] * (1.0f / EE) + 1.1920929e-7f);
    float* yr = y + (size_t)row * EE;
#pragma unroll
    for (int i = 0; i < 3; i++) {
        int c = threadIdx.x + i * 256;
        yr[c] = rnd(vals[i] * r * w[c]);
    }
}

// ---------------- tf32 GEMM, cp.async double-buffered -----------------------
// C = A @ W^T (+epilogues). A:[M,K] rm (tf32-rounded), W:[N,K] rm (rounded)
// flags bit0: relu, bit1: round output to tf32
#define ST 36
#define ATILE (128*ST)      // 4608 floats
#define STG (2*ATILE)       // 9216 floats per stage

__global__ void __launch_bounds__(256, 2) mma_gemm(
    const float* __restrict__ A, const float* __restrict__ B, float* __restrict__ C,
    const float* __restrict__ bias, const float* __restrict__ res,
    const float* __restrict__ inter4, const float* __restrict__ b2,
    int M, int N, int K, int lda, int ldb, int ldc, int flags)
{
    extern __shared__ float dyn[];
    const int tid  = threadIdx.x;
    const int lane = tid & 31, warp = tid >> 5;
    const int g = lane >> 2, t4 = lane & 3;
    const int wm = (warp >> 1) * 32;
    const int wn = (warp & 1) * 64;
    const int mBase = blockIdx.y * 128, nBase = blockIdx.x * 128;
    const int lr = tid >> 3;            // 0..31
    const int kA = (tid & 7) * 4;       // 0,4,..,28

    const unsigned sb = (unsigned)__cvta_generic_to_shared(dyn);

    const float* aP[4];
    const float* bP[4];
    int bSz[4];
#pragma unroll
    for (int r = 0; r < 4; r++) {
        int row = lr + 32 * r;
        aP[r] = A + (size_t)(mBase + row) * lda + kA;
        bool ok = (nBase + row) < N;
        bP[r] = ok ? (B + (size_t)(nBase + row) * ldb + kA) : B;
        bSz[r] = ok ? 16 : 0;
    }

    float acc[2][8][4];
#pragma unroll
    for (int i = 0; i < 2; i++)
#pragma unroll
        for (int j = 0; j < 8; j++)
#pragma unroll
            for (int c = 0; c < 4; c++) acc[i][j][c] = 0.f;

    const int nIter = K >> 5;

    // prologue: issue tile 0
#pragma unroll
    for (int r = 0; r < 4; r++) {
        int row = lr + 32 * r;
        cp16 (sb + (0 * STG + row * ST + kA) * 4, aP[r]);
        cp16z(sb + (0 * STG + ATILE + row * ST + kA) * 4, bP[r], bSz[r]);
        aP[r] += 32; bP[r] += 32;
    }
    cp_commit();

    for (int it = 0; it < nIter; it++) {
        cp_wait0();
        __syncthreads();
        if (it + 1 < nIter) {
            const int nbuf = (it + 1) & 1;
#pragma unroll
            for (int r = 0; r < 4; r++) {
                int row = lr + 32 * r;
                cp16 (sb + (nbuf * STG + row * ST + kA) * 4, aP[r]);
                cp16z(sb + (nbuf * STG + ATILE + row * ST + kA) * 4, bP[r], bSz[r]);
                aP[r] += 32; bP[r] += 32;
            }
            cp_commit();
        }
        const float* As = dyn + (it & 1) * STG;
        const float* Bs = As + ATILE;
#pragma unroll
        for (int kk = 0; kk < 4; kk++) {
            const int kb = kk * 8;
            unsigned a[2][4], b[8][2];
#pragma unroll
            for (int mt = 0; mt < 2; mt++) {
                int mr = wm + mt * 16 + g;
                a[mt][0] = __float_as_uint(As[mr * ST + kb + t4]);
                a[mt][1] = __float_as_uint(As[(mr + 8) * ST + kb + t4]);
                a[mt][2] = __float_as_uint(As[mr * ST + kb + t4 + 4]);
                a[mt][3] = __float_as_uint(As[(mr + 8) * ST + kb + t4 + 4]);
            }
#pragma unroll
            for (int nt = 0; nt < 8; nt++) {
                int nc = wn + nt * 8 + g;
                b[nt][0] = __float_as_uint(Bs[nc * ST + kb + t4]);
                b[nt][1] = __float_as_uint(Bs[nc * ST + kb + t4 + 4]);
            }
#pragma unroll
            for (int mt = 0; mt < 2; mt++)
#pragma unroll
                for (int nt = 0; nt < 8; nt++)
                    mma_tf32(acc[mt][nt], a[mt], b[nt]);
        }
    }

    // --- epilogue
    const bool relu = flags & 1;
    const bool roundC = flags & 2;
#pragma unroll
    for (int mt = 0; mt < 2; mt++) {
#pragma unroll
        for (int half = 0; half < 2; half++) {
            int m = mBase + wm + mt * 16 + g + half * 8;
            float i0 = 0.f, i1 = 0.f, i2 = 0.f, i3 = 0.f;
            if (inter4) {
                const float* ip = inter4 + (size_t)m * 4;
                i0 = ip[0]; i1 = ip[1]; i2 = ip[2]; i3 = ip[3];
            }
#pragma unroll
            for (int nt = 0; nt < 8; nt++) {
#pragma unroll
                for (int c = 0; c < 2; c++) {
                    int n = nBase + wn + nt * 8 + 2 * t4 + c;
                    if (n < N) {
                        float v = acc[mt][nt][half * 2 + c];
                        if (bias) v += bias[n];
                        if (res)  v += res[(size_t)m * ldc + n];
                        if (b2) {
                            const float* bp = b2 + (size_t)n * 4;
                            v += i0 * bp[0] + i1 * bp[1] + i2 * bp[2] + i3 * bp[3];
                        }
                        if (relu) v = fmaxf(v, 0.f);
                        if (roundC) v = rnd(v);
                        C[(size_t)m * ldc + n] = v;
                    }
                }
            }
        }
    }
}

// ---------------- flash attention (cp.async K/V, pre-rounded qkv) -----------
#define QP 68
#define VP 72
#define KVST (64*QP + 64*VP)   // 8960 floats per stage
__global__ void __launch_bounds__(256) flash_attn(
    const float* __restrict__ qkv, float* __restrict__ ctx)
{
    extern __shared__ float pool[];
    const unsigned sb = (unsigned)__cvta_generic_to_shared(pool);

    const int z = blockIdx.y, b = z / HH, h = z % HH;
    const float* base = qkv + (size_t)b * SS * 3 * EE + h * HD;
    const int q0 = blockIdx.x * 128;
    const int tid = threadIdx.x, lane = tid & 31, warp = tid >> 5;
    const int g = lane >> 2, t4 = lane & 3;
    const float qscale = 0.125f * 1.4426950408889634f;  // 1/sqrt(64) * log2(e)

    // ---- stage Q (scaled, tf32) through smem, then load register fragments
#pragma unroll
    for (int r = 0; r < 8; r++) {
        int idx = tid + r * 256;           // 0..2047
        int row = idx >> 4, c4 = (idx & 15) * 4;
        float4 v = *(const float4*)(base + (size_t)(q0 + row) * 3 * EE + c4);
        float4 w;
        w.x = rnd(v.x * qscale);
        w.y = rnd(v.y * qscale);
        w.z = rnd(v.z * qscale);
        w.w = rnd(v.w * qscale);
        *(float4*)(pool + row * QP + c4) = w;
    }
    __syncthreads();
    unsigned qf[8][4];
    const int wq = warp * 16;
#pragma unroll
    for (int kc = 0; kc < 8; kc++) {
        qf[kc][0] = __float_as_uint(pool[(wq + g)     * QP + kc * 8 + t4]);
        qf[kc][1] = __float_as_uint(pool[(wq + g + 8) * QP + kc * 8 + t4]);
        qf[kc][2] = __float_as_uint(pool[(wq + g)     * QP + kc * 8 + t4 + 4]);
        qf[kc][3] = __float_as_uint(pool[(wq + g + 8) * QP + kc * 8 + t4 + 4]);
    }
    __syncthreads();

    float o[8][4];
#pragma unroll
    for (int v = 0; v < 8; v++)
#pragma unroll
        for (int c = 0; c < 4; c++) o[v][c] = 0.f;
    float m0 = -INFINITY, m1 = -INFINITY, l0 = 0.f, l1 = 0.f;

    const int Le = (lane & 28) | (t4 >> 1);
    const int Lo = Le | 2;
    const bool odd = t4 & 1;

    const int frow = tid >> 4, fseg = (tid & 15) * 4;   // K/V copy mapping

    // prologue: issue K/V tile 0
#pragma unroll
    for (int r = 0; r < 4; r++) {
        int row = frow + r * 16;
        const float* kp = base + EE     + (size_t)row * 3 * EE + fseg;
        const float* vp = base + 2 * EE + (size_t)row * 3 * EE + fseg;
        cp16(sb + (row * QP + fseg) * 4, kp);
        cp16(sb + (64 * QP + row * VP + fseg) * 4, vp);
    }
    cp_commit();

    for (int kt = 0; kt < SS / 64; kt++) {
        cp_wait0();
        __syncthreads();
        if (kt + 1 < SS / 64) {
            const int nbuf = (kt + 1) & 1;
#pragma unroll
            for (int r = 0; r < 4; r++) {
                int row = frow + r * 16;
                const float* kp = base + EE     + (size_t)((kt + 1) * 64 + row) * 3 * EE + fseg;
                const float* vp = base + 2 * EE + (size_t)((kt + 1) * 64 + row) * 3 * EE + fseg;
                cp16(sb + (nbuf * KVST + row * QP + fseg) * 4, kp);
                cp16(sb + (nbuf * KVST + 64 * QP + row * VP + fseg) * 4, vp);
            }
            cp_commit();
        }
        const float* Ks = pool + (kt & 1) * KVST;
        const float* Vs = Ks + 64 * QP;

        // ---- scores
        float s[8][4];
#pragma unroll
        for (int j = 0; j < 8; j++)
#pragma unroll
            for (int c = 0; c < 4; c++) s[j][c] = 0.f;
#pragma unroll
        for (int j = 0; j < 8; j++) {
#pragma unroll
            for (int kc = 0; kc < 8; kc++) {
                unsigned bfr[2];
                bfr[0] = __float_as_uint(Ks[(j * 8 + g) * QP + kc * 8 + t4]);
                bfr[1] = __float_as_uint(Ks[(j * 8 + g) * QP + kc * 8 + t4 + 4]);
                mma_tf32(s[j], qf[kc], bfr);
            }
        }

        // ---- online softmax (log2 domain)
        float r0 = -INFINITY, r1 = -INFINITY;
#pragma unroll
        for (int j = 0; j < 8; j++) {
            r0 = fmaxf(r0, fmaxf(s[j][0], s[j][1]));
            r1 = fmaxf(r1, fmaxf(s[j][2], s[j][3]));
        }
        r0 = fmaxf(r0, __shfl_xor_sync(0xffffffffu, r0, 1));
        r0 = fmaxf(r0, __shfl_xor_sync(0xffffffffu, r0, 2));
        r1 = fmaxf(r1, __shfl_xor_sync(0xffffffffu, r1, 1));
        r1 = fmaxf(r1, __shfl_xor_sync(0xffffffffu, r1, 2));
        float m0n = fmaxf(m0, r0), m1n = fmaxf(m1, r1);
        float c0 = exp2f(m0 - m0n), c1 = exp2f(m1 - m1n);
        l0 *= c0; l1 *= c1;
#pragma unroll
        for (int v = 0; v < 8; v++) {
            o[v][0] *= c0; o[v][1] *= c0;
            o[v][2] *= c1; o[v][3] *= c1;
        }
        m0 = m0n; m1 = m1n;
#pragma unroll
        for (int j = 0; j < 8; j++) {
            s[j][0] = exp2f(s[j][0] - m0);
            s[j][1] = exp2f(s[j][1] - m0);
            s[j][2] = exp2f(s[j][2] - m1);
            s[j][3] = exp2f(s[j][3] - m1);
            l0 += s[j][0] + s[j][1];
            l1 += s[j][2] + s[j][3];
        }

        // ---- P.V
#pragma unroll
        for (int j = 0; j < 8; j++) {
            float e0 = __shfl_sync(0xffffffffu, s[j][0], Le);
            float f0 = __shfl_sync(0xffffffffu, s[j][1], Le);
            float e1 = __shfl_sync(0xffffffffu, s[j][2], Le);
            float f1 = __shfl_sync(0xffffffffu, s[j][3], Le);
            float e2 = __shfl_sync(0xffffffffu, s[j][0], Lo);
            float f2 = __shfl_sync(0xffffffffu, s[j][1], Lo);
            float e3 = __shfl_sync(0xffffffffu, s[j][2], Lo);
            float f3 = __shfl_sync(0xffffffffu, s[j][3], Lo);
            unsigned pa[4];
            pa[0] = f2tf32(odd ? f0 : e0);
            pa[1] = f2tf32(odd ? f1 : e1);
            pa[2] = f2tf32(odd ? f2 : e2);
            pa[3] = f2tf32(odd ? f3 : e3);
#pragma unroll
            for (int v = 0; v < 8; v++) {
                unsigned bfr[2];
                bfr[0] = __float_as_uint(Vs[(j * 8 + t4)     * VP + v * 8 + g]);
                bfr[1] = __float_as_uint(Vs[(j * 8 + t4 + 4) * VP + v * 8 + g]);
                mma_tf32(o[v], pa, bfr);
            }
        }
    }

    // ---- finalize (rounded: ctx feeds out_proj GEMM)
    l0 += __shfl_xor_sync(0xffffffffu, l0, 1);
    l0 += __shfl_xor_sync(0xffffffffu, l0, 2);
    l1 += __shfl_xor_sync(0xffffffffu, l1, 1);
    l1 += __shfl_xor_sync(0xffffffffu, l1, 2);
    float inv0 = 1.f / l0, inv1 = 1.f / l1;
    int row0 = q0 + wq + g, row1 = row0 + 8;
    float* c0p = ctx + ((size_t)(b * SS + row0)) * EE + h * HD;
    float* c1p = ctx + ((size_t)(b * SS + row1)) * EE + h * HD;
#pragma unroll
    for (int v = 0; v < 8; v++) {
        int col = v * 8 + 2 * t4;
        float2 w0 = make_float2(rnd(o[v][0] * inv0), rnd(o[v][1] * inv0));
        float2 w1 = make_float2(rnd(o[v][2] * inv1), rnd(o[v][3] * inv1));
        *(float2*)(c0p + col) = w0;
        *(float2*)(c1p + col) = w1;
    }
}

// ---------------- small helper kernels -------------------------------------
__global__ void build_WBt(const float* __restrict__ hB_w2,
                          const float* __restrict__ hB_b2,
                          float* __restrict__ WBt)
{
    int idx = blockIdx.x * 256 + threadIdx.x;
    if (idx >= (RR * HID + RR) * EE) return;
    int n = idx / EE, e = idx % EE;
    float val;
    if (n < RR * HID) {
        int r = n >> 7, h = n & 127;
        val = hB_w2[((size_t)(r * EE + e)) * HID + h];
    } else {
        val = hB_b2[(n - RR * HID) * EE + e];
    }
    WBt[idx] = rnd(val);
}

// merged: inter[m,r] = hB[m,:].v[m,r*128:] + v[m,512+r];  u[m,r*128+h] = inter*hA (rounded)
__global__ void __launch_bounds__(256) interu_kernel(
    const float* __restrict__ v, const float* __restrict__ hB,
    const float* __restrict__ hA, float* __restrict__ inter, float* __restrict__ u)
{
    int wtok = (blockIdx.x * 256 + threadIdx.x) >> 5;
    int lane = threadIdx.x & 31;
    if (wtok >= MM) return;
    const float* vr = v + (size_t)wtok * (RR * HID + RR);
    const float* br = hB + (size_t)wtok * HID;
    float hb[4], ha[4];
#pragma unroll
    for (int j = 0; j < 4; j++) {
        hb[j] = br[lane + j * 32];
        ha[j] = hA[(size_t)wtok * HID + lane + j * 32];
    }
    float iv[RR];
#pragma unroll
    for (int r = 0; r < RR; r++) {
        float s = 0.f;
#pragma unroll
        for (int j = 0; j < 4; j++) s += hb[j] * vr[r * HID + lane + j * 32];
#pragma unroll
        for (int o = 16; o; o >>= 1) s += __shfl_xor_sync(0xffffffffu, s, o);
        iv[r] = s + vr[RR * HID + r];
    }
    if (lane < RR) inter[wtok * RR + lane] = iv[lane];
    float* ur = u + (size_t)wtok * RR * HID;
#pragma unroll
    for (int r = 0; r < RR; r++)
#pragma unroll
        for (int j = 0; j < 4; j++)
            ur[r * HID + lane + j * 32] = rnd(iv[r] * ha[j]);
}

// ---------------- launch ----------------------------------------------------
extern "C" void kernel_launch(void* const* d_in, const int* in_sizes, int n_in,
                              void* d_out, int out_size)
{
    const float* src       = (const float*)d_in[0];
    const float* task      = (const float*)d_in[1];
    const float* norm1_w   = (const float*)d_in[2];
    const float* norm2_w   = (const float*)d_in[3];
    const float* in_proj_w = (const float*)d_in[4];
    const float* out_proj_w= (const float*)d_in[5];
    const float* ffn1_w    = (const float*)d_in[6];
    const float* ffn1_b    = (const float*)d_in[7];
    const float* ffn2_w    = (const float*)d_in[8];
    const float* ffn2_b    = (const float*)d_in[9];
    const float* hA_w1     = (const float*)d_in[10];
    const float* hA_b1     = (const float*)d_in[11];
    const float* hA_w2     = (const float*)d_in[12];
    const float* hA_b2     = (const float*)d_in[13];
    const float* hB_w1     = (const float*)d_in[14];
    const float* hB_b1     = (const float*)d_in[15];
    const float* hB_w2     = (const float*)d_in[16];
    const float* hB_b2     = (const float*)d_in[17];
    float* out = (float*)d_out;

    float *x1, *qkv, *ctx, *src2, *x2, *hA, *hB, *WBt, *v, *inter, *u, *hbuf;
    float *r_task, *r_inproj, *r_outproj, *r_ffn1, *r_ffn2, *r_hAw2, *r_hw1;
    cudaGetSymbolAddress((void**)&x1,   g_x1);
    cudaGetSymbolAddress((void**)&qkv,  g_qkv);
    cudaGetSymbolAddress((void**)&ctx,  g_ctx);
    cudaGetSymbolAddress((void**)&src2, g_src2);
    cudaGetSymbolAddress((void**)&x2,   g_x2);
    cudaGetSymbolAddress((void**)&hA,   g_hA);
    cudaGetSymbolAddress((void**)&hB,   g_hB);
    cudaGetSymbolAddress((void**)&WBt,  g_WBt);
    cudaGetSymbolAddress((void**)&v,    g_v);
    cudaGetSymbolAddress((void**)&inter,g_int);
    cudaGetSymbolAddress((void**)&u,    g_u);
    cudaGetSymbolAddress((void**)&hbuf, g_h);
    cudaGetSymbolAddress((void**)&r_task,   g_r_task);
    cudaGetSymbolAddress((void**)&r_inproj, g_r_inproj);
    cudaGetSymbolAddress((void**)&r_outproj,g_r_outproj);
    cudaGetSymbolAddress((void**)&r_ffn1,   g_r_ffn1);
    cudaGetSymbolAddress((void**)&r_ffn2,   g_r_ffn2);
    cudaGetSymbolAddress((void**)&r_hAw2,   g_r_hAw2);
    cudaGetSymbolAddress((void**)&r_hw1,    g_r_hw1);

    const int DS = 2 * STG * 4;                 // 73728 B
    const int FS = 2 * KVST * 4;                // 71680 B
    cudaFuncSetAttribute(mma_gemm,  cudaFuncAttributeMaxDynamicSharedMemorySize, DS);
    cudaFuncSetAttribute(flash_attn, cudaFuncAttributeMaxDynamicSharedMemorySize, FS);

    // 0) pre-round all GEMM operands to tf32
    auto rr = [&](const float* in, float* o, int n) {
        round_tf32<<<(n / 4 + 255) / 256, 256>>>(in, o, n / 4);
    };
    rr(task,      r_task,    MM * TT);
    rr(in_proj_w, r_inproj,  3 * EE * EE);
    rr(out_proj_w,r_outproj, EE * EE);
    rr(ffn1_w,    r_ffn1,    FF * EE);
    rr(ffn2_w,    r_ffn2,    EE * FF);
    rr(hA_w2,     r_hAw2,    FF * RR * HID);
    rr(hA_w1,     r_hw1,     HID * TT);
    rr(hB_w1,     r_hw1 + HID * TT, HID * TT);

    // 1) x1 = rmsnorm(src, norm1_w) (rounded)
    rmsnorm_kernel<<<MM, 256>>>(src, norm1_w, x1);

    // 2) qkv = x1 @ in_proj^T (rounded out)
    mma_gemm<<<dim3(18, 32), 256, DS>>>(
        x1, r_inproj, qkv, nullptr, nullptr, nullptr, nullptr,
        MM, 3 * EE, EE, EE, EE, 3 * EE, 2);

    // 3) flash attention -> ctx (rounded)
    flash_attn<<<dim3(SS / 128, BB * HH), 256, FS>>>(qkv, ctx);

    // 4) src2 = src + ctx @ out_proj^T
    mma_gemm<<<dim3(6, 32), 256, DS>>>(
        ctx, r_outproj, src2, nullptr, src, nullptr, nullptr,
        MM, EE, EE, EE, EE, EE, 0);

    // 5) x2 = rmsnorm(src2) (rounded)
    rmsnorm_kernel<<<MM, 256>>>(src2, norm2_w, x2);

    // 6) hypernet hiddens
    mma_gemm<<<dim3(1, 32), 256, DS>>>(
        r_task, r_hw1, hA, hA_b1, nullptr, nullptr, nullptr,
        MM, HID, TT, TT, TT, HID, 1);
    mma_gemm<<<dim3(1, 32), 256, DS>>>(
        r_task, r_hw1 + HID * TT, hB, hB_b1, nullptr, nullptr, nullptr,
        MM, HID, TT, TT, TT, HID, 1);

    // 7) rearranged B-side weights (rounded)
    build_WBt<<<((RR * HID + RR) * EE + 255) / 256, 256>>>(hB_w2, hB_b2, WBt);

    // 8) v = x2 @ WBt^T  [4096, 516]
    mma_gemm<<<dim3(5, 32), 256, DS>>>(
        x2, WBt, v, nullptr, nullptr, nullptr, nullptr,
        MM, RR * HID + RR, EE, EE, EE, RR * HID + RR, 0);

    // 9+10) inter + u (rounded)
    interu_kernel<<<MM / 8, 256>>>(v, hB, hA, inter, u);

    // 11) hbuf = x2 @ ffn1^T + b
    mma_gemm<<<dim3(24, 32), 256, DS>>>(
        x2, r_ffn1, hbuf, ffn1_b, nullptr, nullptr, nullptr,
        MM, FF, EE, EE, EE, FF, 0);

    // 12) hbuf = relu(hbuf + u @ hA_w2^T + lora bias) (rounded out)
    mma_gemm<<<dim3(24, 32), 256, DS>>>(
        u, r_hAw2, hbuf, nullptr, hbuf, inter, hA_b2,
        MM, FF, RR * HID, RR * HID, RR * HID, FF, 3);

    // 13) out = src2 + hbuf @ ffn2^T + b
    mma_gemm<<<dim3(6, 32), 256, DS>>>(
        hbuf, r_ffn2, out, ffn2_b, src2, nullptr, nullptr,
        MM, EE, FF, FF, FF, EE, 0);
}

// round 5
// speedup vs baseline: 3.6796x; 1.5703x over previous
#include <cuda_runtime.h>
#include <cuda_bf16.h>
#include <math.h>

// Problem constants
#define BB 2
#define SS 2048
#define EE 768
#define FF 3072
#define RR 4
#define TT 128
#define HH 12
#define HD 64
#define HID 128
#define MM (BB*SS)          // 4096 tokens

// ---------------- scratch (device globals; no cudaMalloc allowed) ----------
__device__ float g_x1  [MM*EE];
__device__ float g_qkv [MM*3*EE];
__device__ float g_ctx [MM*EE];
__device__ float g_src2[MM*EE];
__device__ float g_x2  [MM*EE];
__device__ float g_hA  [MM*HID];
__device__ float g_hB  [MM*HID];
__device__ float g_WBt [(RR*HID+RR)*EE];
__device__ float g_v   [MM*(RR*HID+RR)];
__device__ float g_int [MM*RR];
__device__ float g_u   [MM*RR*HID];
__device__ float g_h   [MM*FF];
// rounded copies of GEMM operands
__device__ float g_r_task  [MM*TT];
__device__ float g_r_inproj[3*EE*EE];
__device__ float g_r_outproj[EE*EE];
__device__ float g_r_ffn1  [FF*EE];
__device__ float g_r_ffn2  [EE*FF];
__device__ float g_r_hAw2  [FF*RR*HID];
__device__ float g_r_hw1   [2*HID*TT];

// ---------------- helpers ---------------------------------------------------
__device__ __forceinline__ unsigned f2tf32(float f) {
    unsigned u;
    asm("cvt.rna.tf32.f32 %0, %1;" : "=r"(u) : "f"(f));
    return u;
}
__device__ __forceinline__ float rnd(float f) { return __uint_as_float(f2tf32(f)); }

__device__ __forceinline__ void mma_tf32(float c[4], const unsigned a[4], const unsigned b[2]) {
    asm volatile(
        "mma.sync.aligned.m16n8k8.row.col.f32.tf32.tf32.f32 "
        "{%0,%1,%2,%3}, {%4,%5,%6,%7}, {%8,%9}, {%0,%1,%2,%3};\n"
        : "+f"(c[0]), "+f"(c[1]), "+f"(c[2]), "+f"(c[3])
        : "r"(a[0]), "r"(a[1]), "r"(a[2]), "r"(a[3]), "r"(b[0]), "r"(b[1]));
}

__device__ __forceinline__ void cp16(unsigned dst, const float* src) {
    asm volatile("cp.async.cg.shared.global [%0], [%1], 16;\n" :: "r"(dst), "l"(src));
}
__device__ __forceinline__ void cp16z(unsigned dst, const float* src, int sz) {
    asm volatile("cp.async.cg.shared.global [%0], [%1], 16, %2;\n" :: "r"(dst), "l"(src), "r"(sz));
}
__device__ __forceinline__ void cp_commit() { asm volatile("cp.async.commit_group;\n"); }
__device__ __forceinline__ void cp_wait0()  { asm volatile("cp.async.wait_group 0;\n"); }
__device__ __forceinline__ void cp_wait1()  { asm volatile("cp.async.wait_group 1;\n"); }

// ---------------- batched rounding pass (all weights, one launch) ----------
struct RTab {
    const float* s[8];
    float* d[8];
    int end[8];          // cumulative end, in float4 units
};

__global__ void __launch_bounds__(256) round_all(RTab t, int total4)
{
    int i = blockIdx.x * 256 + threadIdx.x;
    if (i >= total4) return;
    int j = 0;
    while (i >= t.end[j]) j++;
    int off = i - (j ? t.end[j - 1] : 0);
    float4 v = ((const float4*)t.s[j])[off];
    v.x = rnd(v.x); v.y = rnd(v.y); v.z = rnd(v.z); v.w = rnd(v.w);
    ((float4*)t.d[j])[off] = v;
}

// ---------------- rmsnorm (output rounded to tf32) --------------------------
__global__ void __launch_bounds__(256) rmsnorm_kernel(
    const float* __restrict__ x, const float* __restrict__ w, float* __restrict__ y)
{
    int row = blockIdx.x;
    const float* xr = x + (size_t)row * EE;
    float vals[3];
    float s = 0.f;
#pragma unroll
    for (int i = 0; i < 3; i++) {
        vals[i] = xr[threadIdx.x + i * 256];
        s += vals[i] * vals[i];
    }
#pragma unroll
    for (int o = 16; o; o >>= 1) s += __shfl_down_sync(0xffffffffu, s, o);
    __shared__ float red[8];
    if ((threadIdx.x & 31) == 0) red[threadIdx.x >> 5] = s;
    __syncthreads();
    if (threadIdx.x < 8) {
        float t = red[threadIdx.x];
#pragma unroll
        for (int o = 4; o; o >>= 1) t += __shfl_down_sync(0xffu, t, o);
        if (threadIdx.x == 0) red[0] = t;
    }
    __syncthreads();
    float r = rsqrtf(red[0] * (1.0f / EE) + 1.1920929e-7f);
    float* yr = y + (size_t)row * EE;
#pragma unroll
    for (int i = 0; i < 3; i++) {
        int c = threadIdx.x + i * 256;
        yr[c] = rnd(vals[i] * r * w[c]);
    }
}

// ---------------- tf32 GEMM, cp.async 3-stage pipeline ----------------------
// C = A @ W^T over K, then optionally + A2 @ B2^T over K2 (dual-K accumulate)
// flags bit0: relu, bit1: round output to tf32
// blockIdx.z==1 selects (Bz,biasz,Cz) alternate problem (same A/M/N/K)
#define ST 36
#define ATILE (128*ST)      // 4608 floats
#define STG (2*ATILE)       // 9216 floats per stage

__global__ void __launch_bounds__(256, 2) mma_gemm(
    const float* __restrict__ A, const float* __restrict__ B, float* __restrict__ C,
    const float* __restrict__ bias, const float* __restrict__ res,
    const float* __restrict__ inter4, const float* __restrict__ b2,
    const float* __restrict__ A2, const float* __restrict__ B2,
    int K2, int lda2, int ldb2,
    const float* __restrict__ Bz, const float* __restrict__ biasz, float* __restrict__ Cz,
    int M, int N, int K, int lda, int ldb, int ldc, int flags)
{
    extern __shared__ float dyn[];
    if (blockIdx.z == 1) { B = Bz; bias = biasz; C = Cz; }

    const int tid  = threadIdx.x;
    const int lane = tid & 31, warp = tid >> 5;
    const int g = lane >> 2, t4 = lane & 3;
    const int wm = (warp >> 1) * 32;
    const int wn = (warp & 1) * 64;
    const int mBase = blockIdx.y * 128, nBase = blockIdx.x * 128;
    const int lr = tid >> 3;            // 0..31
    const int kA = (tid & 7) * 4;       // 0,4,..,28

    const unsigned sb = (unsigned)__cvta_generic_to_shared(dyn);

    const int n1 = K >> 5, n2 = K2 >> 5, nT = n1 + n2;

    float acc[2][8][4];
#pragma unroll
    for (int i = 0; i < 2; i++)
#pragma unroll
        for (int j = 0; j < 8; j++)
#pragma unroll
            for (int c = 0; c < 4; c++) acc[i][j][c] = 0.f;

    // issue copy of logical tile t into smem stage buf
    auto issue = [&](int t, int buf) {
        const float* Ab; const float* Bb; int la, lb, k0;
        if (t < n1) { Ab = A;  Bb = B;  la = lda;  lb = ldb;  k0 = t * 32; }
        else        { Ab = A2; Bb = B2; la = lda2; lb = ldb2; k0 = (t - n1) * 32; }
#pragma unroll
        for (int r = 0; r < 4; r++) {
            int row = lr + 32 * r;
            const float* ap = Ab + (size_t)(mBase + row) * la + k0 + kA;
            bool ok = (nBase + row) < N;
            const float* bp = ok ? (Bb + (size_t)(nBase + row) * lb + k0 + kA) : Bb;
            cp16 (sb + (buf * STG + row * ST + kA) * 4, ap);
            cp16z(sb + (buf * STG + ATILE + row * ST + kA) * 4, bp, ok ? 16 : 0);
        }
        cp_commit();
    };

    // prologue: stage tiles 0 and 1
    issue(0, 0);
    if (nT > 1) issue(1, 1);

    for (int t = 0; t < nT; t++) {
        if (t < nT - 1) cp_wait1(); else cp_wait0();
        __syncthreads();
        if (t + 2 < nT) issue(t + 2, (t + 2) % 3);

        const float* As = dyn + (t % 3) * STG;
        const float* Bs = As + ATILE;
#pragma unroll
        for (int kk = 0; kk < 4; kk++) {
            const int kb = kk * 8;
            unsigned a[2][4], b[8][2];
#pragma unroll
            for (int mt = 0; mt < 2; mt++) {
                int mr = wm + mt * 16 + g;
                a[mt][0] = __float_as_uint(As[mr * ST + kb + t4]);
                a[mt][1] = __float_as_uint(As[(mr + 8) * ST + kb + t4]);
                a[mt][2] = __float_as_uint(As[mr * ST + kb + t4 + 4]);
                a[mt][3] = __float_as_uint(As[(mr + 8) * ST + kb + t4 + 4]);
            }
#pragma unroll
            for (int nt = 0; nt < 8; nt++) {
                int nc = wn + nt * 8 + g;
                b[nt][0] = __float_as_uint(Bs[nc * ST + kb + t4]);
                b[nt][1] = __float_as_uint(Bs[nc * ST + kb + t4 + 4]);
            }
#pragma unroll
            for (int mt = 0; mt < 2; mt++)
#pragma unroll
                for (int nt = 0; nt < 8; nt++)
                    mma_tf32(acc[mt][nt], a[mt], b[nt]);
        }
    }

    // --- epilogue
    const bool relu = flags & 1;
    const bool roundC = flags & 2;
#pragma unroll
    for (int mt = 0; mt < 2; mt++) {
#pragma unroll
        for (int half = 0; half < 2; half++) {
            int m = mBase + wm + mt * 16 + g + half * 8;
            float i0 = 0.f, i1 = 0.f, i2 = 0.f, i3 = 0.f;
            if (inter4) {
                const float* ip = inter4 + (size_t)m * 4;
                i0 = ip[0]; i1 = ip[1]; i2 = ip[2]; i3 = ip[3];
            }
#pragma unroll
            for (int nt = 0; nt < 8; nt++) {
#pragma unroll
                for (int c = 0; c < 2; c++) {
                    int n = nBase + wn + nt * 8 + 2 * t4 + c;
                    if (n < N) {
                        float v = acc[mt][nt][half * 2 + c];
                        if (bias) v += bias[n];
                        if (res)  v += res[(size_t)m * ldc + n];
                        if (b2) {
                            const float* bp = b2 + (size_t)n * 4;
                            v += i0 * bp[0] + i1 * bp[1] + i2 * bp[2] + i3 * bp[3];
                        }
                        if (relu) v = fmaxf(v, 0.f);
                        if (roundC) v = rnd(v);
                        C[(size_t)m * ldc + n] = v;
                    }
                }
            }
        }
    }
}

// ---------------- flash attention (cp.async K/V, pre-rounded qkv) -----------
#define QP 68
#define VP 72
#define KVST (64*QP + 64*VP)   // 8960 floats per stage
__global__ void __launch_bounds__(256) flash_attn(
    const float* __restrict__ qkv, float* __restrict__ ctx)
{
    extern __shared__ float pool[];
    const unsigned sb = (unsigned)__cvta_generic_to_shared(pool);

    const int z = blockIdx.y, b = z / HH, h = z % HH;
    const float* base = qkv + (size_t)b * SS * 3 * EE + h * HD;
    const int q0 = blockIdx.x * 128;
    const int tid = threadIdx.x, lane = tid & 31, warp = tid >> 5;
    const int g = lane >> 2, t4 = lane & 3;
    const float qscale = 0.125f * 1.4426950408889634f;  // 1/sqrt(64) * log2(e)

    // ---- stage Q (scaled, tf32) through smem, then load register fragments
#pragma unroll
    for (int r = 0; r < 8; r++) {
        int idx = tid + r * 256;           // 0..2047
        int row = idx >> 4, c4 = (idx & 15) * 4;
        float4 v = *(const float4*)(base + (size_t)(q0 + row) * 3 * EE + c4);
        float4 w;
        w.x = rnd(v.x * qscale);
        w.y = rnd(v.y * qscale);
        w.z = rnd(v.z * qscale);
        w.w = rnd(v.w * qscale);
        *(float4*)(pool + row * QP + c4) = w;
    }
    __syncthreads();
    unsigned qf[8][4];
    const int wq = warp * 16;
#pragma unroll
    for (int kc = 0; kc < 8; kc++) {
        qf[kc][0] = __float_as_uint(pool[(wq + g)     * QP + kc * 8 + t4]);
        qf[kc][1] = __float_as_uint(pool[(wq + g + 8) * QP + kc * 8 + t4]);
        qf[kc][2] = __float_as_uint(pool[(wq + g)     * QP + kc * 8 + t4 + 4]);
        qf[kc][3] = __float_as_uint(pool[(wq + g + 8) * QP + kc * 8 + t4 + 4]);
    }
    __syncthreads();

    float o[8][4];
#pragma unroll
    for (int v = 0; v < 8; v++)
#pragma unroll
        for (int c = 0; c < 4; c++) o[v][c] = 0.f;
    float m0 = -INFINITY, m1 = -INFINITY, l0 = 0.f, l1 = 0.f;

    const int Le = (lane & 28) | (t4 >> 1);
    const int Lo = Le | 2;
    const bool odd = t4 & 1;

    const int frow = tid >> 4, fseg = (tid & 15) * 4;   // K/V copy mapping

    // prologue: issue K/V tile 0
#pragma unroll
    for (int r = 0; r < 4; r++) {
        int row = frow + r * 16;
        const float* kp = base + EE     + (size_t)row * 3 * EE + fseg;
        const float* vp = base + 2 * EE + (size_t)row * 3 * EE + fseg;
        cp16(sb + (row * QP + fseg) * 4, kp);
        cp16(sb + (64 * QP + row * VP + fseg) * 4, vp);
    }
    cp_commit();

    for (int kt = 0; kt < SS / 64; kt++) {
        cp_wait0();
        __syncthreads();
        if (kt + 1 < SS / 64) {
            const int nbuf = (kt + 1) & 1;
#pragma unroll
            for (int r = 0; r < 4; r++) {
                int row = frow + r * 16;
                const float* kp = base + EE     + (size_t)((kt + 1) * 64 + row) * 3 * EE + fseg;
                const float* vp = base + 2 * EE + (size_t)((kt + 1) * 64 + row) * 3 * EE + fseg;
                cp16(sb + (nbuf * KVST + row * QP + fseg) * 4, kp);
                cp16(sb + (nbuf * KVST + 64 * QP + row * VP + fseg) * 4, vp);
            }
            cp_commit();
        }
        const float* Ks = pool + (kt & 1) * KVST;
        const float* Vs = Ks + 64 * QP;

        // ---- scores
        float s[8][4];
#pragma unroll
        for (int j = 0; j < 8; j++)
#pragma unroll
            for (int c = 0; c < 4; c++) s[j][c] = 0.f;
#pragma unroll
        for (int j = 0; j < 8; j++) {
#pragma unroll
            for (int kc = 0; kc < 8; kc++) {
                unsigned bfr[2];
                bfr[0] = __float_as_uint(Ks[(j * 8 + g) * QP + kc * 8 + t4]);
                bfr[1] = __float_as_uint(Ks[(j * 8 + g) * QP + kc * 8 + t4 + 4]);
                mma_tf32(s[j], qf[kc], bfr);
            }
        }

        // ---- online softmax (log2 domain)
        float r0 = -INFINITY, r1 = -INFINITY;
#pragma unroll
        for (int j = 0; j < 8; j++) {
            r0 = fmaxf(r0, fmaxf(s[j][0], s[j][1]));
            r1 = fmaxf(r1, fmaxf(s[j][2], s[j][3]));
        }
        r0 = fmaxf(r0, __shfl_xor_sync(0xffffffffu, r0, 1));
        r0 = fmaxf(r0, __shfl_xor_sync(0xffffffffu, r0, 2));
        r1 = fmaxf(r1, __shfl_xor_sync(0xffffffffu, r1, 1));
        r1 = fmaxf(r1, __shfl_xor_sync(0xffffffffu, r1, 2));
        float m0n = fmaxf(m0, r0), m1n = fmaxf(m1, r1);
        float c0 = exp2f(m0 - m0n), c1 = exp2f(m1 - m1n);
        l0 *= c0; l1 *= c1;
#pragma unroll
        for (int v = 0; v < 8; v++) {
            o[v][0] *= c0; o[v][1] *= c0;
            o[v][2] *= c1; o[v][3] *= c1;
        }
        m0 = m0n; m1 = m1n;
#pragma unroll
        for (int j = 0; j < 8; j++) {
            s[j][0] = exp2f(s[j][0] - m0);
            s[j][1] = exp2f(s[j][1] - m0);
            s[j][2] = exp2f(s[j][2] - m1);
            s[j][3] = exp2f(s[j][3] - m1);
            l0 += s[j][0] + s[j][1];
            l1 += s[j][2] + s[j][3];
        }

        // ---- P.V
#pragma unroll
        for (int j = 0; j < 8; j++) {
            float e0 = __shfl_sync(0xffffffffu, s[j][0], Le);
            float f0 = __shfl_sync(0xffffffffu, s[j][1], Le);
            float e1 = __shfl_sync(0xffffffffu, s[j][2], Le);
            float f1 = __shfl_sync(0xffffffffu, s[j][3], Le);
            float e2 = __shfl_sync(0xffffffffu, s[j][0], Lo);
            float f2 = __shfl_sync(0xffffffffu, s[j][1], Lo);
            float e3 = __shfl_sync(0xffffffffu, s[j][2], Lo);
            float f3 = __shfl_sync(0xffffffffu, s[j][3], Lo);
            unsigned pa[4];
            pa[0] = f2tf32(odd ? f0 : e0);
            pa[1] = f2tf32(odd ? f1 : e1);
            pa[2] = f2tf32(odd ? f2 : e2);
            pa[3] = f2tf32(odd ? f3 : e3);
#pragma unroll
            for (int v = 0; v < 8; v++) {
                unsigned bfr[2];
                bfr[0] = __float_as_uint(Vs[(j * 8 + t4)     * VP + v * 8 + g]);
                bfr[1] = __float_as_uint(Vs[(j * 8 + t4 + 4) * VP + v * 8 + g]);
                mma_tf32(o[v], pa, bfr);
            }
        }
    }

    // ---- finalize (rounded: ctx feeds out_proj GEMM)
    l0 += __shfl_xor_sync(0xffffffffu, l0, 1);
    l0 += __shfl_xor_sync(0xffffffffu, l0, 2);
    l1 += __shfl_xor_sync(0xffffffffu, l1, 1);
    l1 += __shfl_xor_sync(0xffffffffu, l1, 2);
    float inv0 = 1.f / l0, inv1 = 1.f / l1;
    int row0 = q0 + wq + g, row1 = row0 + 8;
    float* c0p = ctx + ((size_t)(b * SS + row0)) * EE + h * HD;
    float* c1p = ctx + ((size_t)(b * SS + row1)) * EE + h * HD;
#pragma unroll
    for (int v = 0; v < 8; v++) {
        int col = v * 8 + 2 * t4;
        float2 w0 = make_float2(rnd(o[v][0] * inv0), rnd(o[v][1] * inv0));
        float2 w1 = make_float2(rnd(o[v][2] * inv1), rnd(o[v][3] * inv1));
        *(float2*)(c0p + col) = w0;
        *(float2*)(c1p + col) = w1;
    }
}

// ---------------- small helper kernels -------------------------------------
__global__ void build_WBt(const float* __restrict__ hB_w2,
                          const float* __restrict__ hB_b2,
                          float* __restrict__ WBt)
{
    int idx = blockIdx.x * 256 + threadIdx.x;
    if (idx >= (RR * HID + RR) * EE) return;
    int n = idx / EE, e = idx % EE;
    float val;
    if (n < RR * HID) {
        int r = n >> 7, h = n & 127;
        val = hB_w2[((size_t)(r * EE + e)) * HID + h];
    } else {
        val = hB_b2[(n - RR * HID) * EE + e];
    }
    WBt[idx] = rnd(val);
}

// merged: inter[m,r] = hB[m,:].v[m,r*128:] + v[m,512+r];  u[m,r*128+h] = inter*hA (rounded)
__global__ void __launch_bounds__(256) interu_kernel(
    const float* __restrict__ v, const float* __restrict__ hB,
    const float* __restrict__ hA, float* __restrict__ inter, float* __restrict__ u)
{
    int wtok = (blockIdx.x * 256 + threadIdx.x) >> 5;
    int lane = threadIdx.x & 31;
    if (wtok >= MM) return;
    const float* vr = v + (size_t)wtok * (RR * HID + RR);
    const float* br = hB + (size_t)wtok * HID;
    float hb[4], ha[4];
#pragma unroll
    for (int j = 0; j < 4; j++) {
        hb[j] = br[lane + j * 32];
        ha[j] = hA[(size_t)wtok * HID + lane + j * 32];
    }
    float iv[RR];
#pragma unroll
    for (int r = 0; r < RR; r++) {
        float s = 0.f;
#pragma unroll
        for (int j = 0; j < 4; j++) s += hb[j] * vr[r * HID + lane + j * 32];
#pragma unroll
        for (int o = 16; o; o >>= 1) s += __shfl_xor_sync(0xffffffffu, s, o);
        iv[r] = s + vr[RR * HID + r];
    }
    if (lane < RR) inter[wtok * RR + lane] = iv[lane];
    float* ur = u + (size_t)wtok * RR * HID;
#pragma unroll
    for (int r = 0; r < RR; r++)
#pragma unroll
        for (int j = 0; j < 4; j++)
            ur[r * HID + lane + j * 32] = rnd(iv[r] * ha[j]);
}

// ---------------- launch ----------------------------------------------------
extern "C" void kernel_launch(void* const* d_in, const int* in_sizes, int n_in,
                              void* d_out, int out_size)
{
    const float* src       = (const float*)d_in[0];
    const float* task      = (const float*)d_in[1];
    const float* norm1_w   = (const float*)d_in[2];
    const float* norm2_w   = (const float*)d_in[3];
    const float* in_proj_w = (const float*)d_in[4];
    const float* out_proj_w= (const float*)d_in[5];
    const float* ffn1_w    = (const float*)d_in[6];
    const float* ffn1_b    = (const float*)d_in[7];
    const float* ffn2_w    = (const float*)d_in[8];
    const float* ffn2_b    = (const float*)d_in[9];
    const float* hA_w1     = (const float*)d_in[10];
    const float* hA_b1     = (const float*)d_in[11];
    const float* hA_w2     = (const float*)d_in[12];
    const float* hA_b2     = (const float*)d_in[13];
    const float* hB_w1     = (const float*)d_in[14];
    const float* hB_b1     = (const float*)d_in[15];
    const float* hB_w2     = (const float*)d_in[16];
    const float* hB_b2     = (const float*)d_in[17];
    float* out = (float*)d_out;

    float *x1, *qkv, *ctx, *src2, *x2, *hA, *hB, *WBt, *v, *inter, *u, *hbuf;
    float *r_task, *r_inproj, *r_outproj, *r_ffn1, *r_ffn2, *r_hAw2, *r_hw1;
    cudaGetSymbolAddress((void**)&x1,   g_x1);
    cudaGetSymbolAddress((void**)&qkv,  g_qkv);
    cudaGetSymbolAddress((void**)&ctx,  g_ctx);
    cudaGetSymbolAddress((void**)&src2, g_src2);
    cudaGetSymbolAddress((void**)&x2,   g_x2);
    cudaGetSymbolAddress((void**)&hA,   g_hA);
    cudaGetSymbolAddress((void**)&hB,   g_hB);
    cudaGetSymbolAddress((void**)&WBt,  g_WBt);
    cudaGetSymbolAddress((void**)&v,    g_v);
    cudaGetSymbolAddress((void**)&inter,g_int);
    cudaGetSymbolAddress((void**)&u,    g_u);
    cudaGetSymbolAddress((void**)&hbuf, g_h);
    cudaGetSymbolAddress((void**)&r_task,   g_r_task);
    cudaGetSymbolAddress((void**)&r_inproj, g_r_inproj);
    cudaGetSymbolAddress((void**)&r_outproj,g_r_outproj);
    cudaGetSymbolAddress((void**)&r_ffn1,   g_r_ffn1);
    cudaGetSymbolAddress((void**)&r_ffn2,   g_r_ffn2);
    cudaGetSymbolAddress((void**)&r_hAw2,   g_r_hAw2);
    cudaGetSymbolAddress((void**)&r_hw1,    g_r_hw1);

    const int DS = 3 * STG * 4;                 // 110592 B (3-stage)
    const int FS = 2 * KVST * 4;                // 71680 B
    cudaFuncSetAttribute(mma_gemm,  cudaFuncAttributeMaxDynamicSharedMemorySize, DS);
    cudaFuncSetAttribute(flash_attn, cudaFuncAttributeMaxDynamicSharedMemorySize, FS);

    // 0) pre-round all GEMM operands to tf32 (one launch)
    {
        RTab t;
        const float* ss[8] = {task, in_proj_w, out_proj_w, ffn1_w, ffn2_w, hA_w2, hA_w1, hB_w1};
        float* dd[8] = {r_task, r_inproj, r_outproj, r_ffn1, r_ffn2, r_hAw2, r_hw1, r_hw1 + HID * TT};
        int nn[8] = {MM * TT / 4, 3 * EE * EE / 4, EE * EE / 4, FF * EE / 4,
                     EE * FF / 4, FF * RR * HID / 4, HID * TT / 4, HID * TT / 4};
        int cum = 0;
        for (int j = 0; j < 8; j++) { t.s[j] = ss[j]; t.d[j] = dd[j]; cum += nn[j]; t.end[j] = cum; }
        round_all<<<(cum + 255) / 256, 256>>>(t, cum);
    }

    // 1) x1 = rmsnorm(src, norm1_w) (rounded)
    rmsnorm_kernel<<<MM, 256>>>(src, norm1_w, x1);

    // 2) qkv = x1 @ in_proj^T (rounded out)
    mma_gemm<<<dim3(18, 32, 1), 256, DS>>>(
        x1, r_inproj, qkv, nullptr, nullptr, nullptr, nullptr,
        nullptr, nullptr, 0, 0, 0, nullptr, nullptr, nullptr,
        MM, 3 * EE, EE, EE, EE, 3 * EE, 2);

    // 3) flash attention -> ctx (rounded)
    flash_attn<<<dim3(SS / 128, BB * HH), 256, FS>>>(qkv, ctx);

    // 4) src2 = src + ctx @ out_proj^T
    mma_gemm<<<dim3(6, 32, 1), 256, DS>>>(
        ctx, r_outproj, src2, nullptr, src, nullptr, nullptr,
        nullptr, nullptr, 0, 0, 0, nullptr, nullptr, nullptr,
        MM, EE, EE, EE, EE, EE, 0);

    // 5) x2 = rmsnorm(src2) (rounded)
    rmsnorm_kernel<<<MM, 256>>>(src2, norm2_w, x2);

    // 6) hypernet hiddens hA & hB in one launch (z selects problem)
    mma_gemm<<<dim3(1, 32, 2), 256, DS>>>(
        r_task, r_hw1, hA, hA_b1, nullptr, nullptr, nullptr,
        nullptr, nullptr, 0, 0, 0,
        r_hw1 + HID * TT, hB_b1, hB,
        MM, HID, TT, TT, TT, HID, 1);

    // 7) rearranged B-side weights (rounded)
    build_WBt<<<((RR * HID + RR) * EE + 255) / 256, 256>>>(hB_w2, hB_b2, WBt);

    // 8) v = x2 @ WBt^T  [4096, 516]
    mma_gemm<<<dim3(5, 32, 1), 256, DS>>>(
        x2, WBt, v, nullptr, nullptr, nullptr, nullptr,
        nullptr, nullptr, 0, 0, 0, nullptr, nullptr, nullptr,
        MM, RR * HID + RR, EE, EE, EE, RR * HID + RR, 0);

    // 9) inter + u (rounded)
    interu_kernel<<<MM / 8, 256>>>(v, hB, hA, inter, u);

    // 10) fused FFN1 + LoRA expand: hbuf = relu(x2@ffn1^T + u@hAw2^T + ffn1_b + lora_b), rounded
    mma_gemm<<<dim3(24, 32, 1), 256, DS>>>(
        x2, r_ffn1, hbuf, ffn1_b, nullptr, inter, hA_b2,
        u, r_hAw2, RR * HID, RR * HID, RR * HID,
        nullptr, nullptr, nullptr,
        MM, FF, EE, EE, EE, FF, 3);

    // 11) out = src2 + hbuf @ ffn2^T + ffn2_b
    mma_gemm<<<dim3(6, 32, 1), 256, DS>>>(
        hbuf, r_ffn2, out, ffn2_b, src2, nullptr, nullptr,
        nullptr, nullptr, 0, 0, 0, nullptr, nullptr, nullptr,
        MM, EE, FF, FF, FF, EE, 0);
}

// round 6
// speedup vs baseline: 3.7783x; 1.0268x over previous
#include <cuda_runtime.h>
#include <cuda_bf16.h>
#include <math.h>

// Problem constants
#define BB 2
#define SS 2048
#define EE 768
#define FF 3072
#define RR 4
#define TT 128
#define HH 12
#define HD 64
#define HID 128
#define MM (BB*SS)          // 4096 tokens

// ---------------- scratch (device globals; no cudaMalloc allowed) ----------
__device__ float g_x1  [MM*EE];
__device__ float g_qkv [MM*3*EE];
__device__ float g_ctx [MM*EE];
__device__ float g_src2[MM*EE];
__device__ float g_x2  [MM*EE];
__device__ float g_hA  [MM*HID];
__device__ float g_hB  [MM*HID];
__device__ float g_WBt [(RR*HID+RR)*EE];
__device__ float g_v   [MM*(RR*HID+RR)];
__device__ float g_int [MM*RR];
__device__ float g_u   [MM*RR*HID];
__device__ float g_h   [MM*FF];
// rounded copies of GEMM operands
__device__ float g_r_task  [MM*TT];
__device__ float g_r_inproj[3*EE*EE];
__device__ float g_r_outproj[EE*EE];
__device__ float g_r_ffn1  [FF*EE];
__device__ float g_r_ffn2  [EE*FF];
__device__ float g_r_hAw2  [FF*RR*HID];
__device__ float g_r_hw1   [2*HID*TT];

// ---------------- helpers ---------------------------------------------------
__device__ __forceinline__ unsigned f2tf32(float f) {
    unsigned u;
    asm("cvt.rna.tf32.f32 %0, %1;" : "=r"(u) : "f"(f));
    return u;
}
__device__ __forceinline__ float rnd(float f) { return __uint_as_float(f2tf32(f)); }

__device__ __forceinline__ void mma_tf32(float c[4], const unsigned a[4], const unsigned b[2]) {
    asm volatile(
        "mma.sync.aligned.m16n8k8.row.col.f32.tf32.tf32.f32 "
        "{%0,%1,%2,%3}, {%4,%5,%6,%7}, {%8,%9}, {%0,%1,%2,%3};\n"
        : "+f"(c[0]), "+f"(c[1]), "+f"(c[2]), "+f"(c[3])
        : "r"(a[0]), "r"(a[1]), "r"(a[2]), "r"(a[3]), "r"(b[0]), "r"(b[1]));
}

__device__ __forceinline__ void cp16(unsigned dst, const float* src) {
    asm volatile("cp.async.cg.shared.global [%0], [%1], 16;\n" :: "r"(dst), "l"(src));
}
__device__ __forceinline__ void cp16z(unsigned dst, const float* src, int sz) {
    asm volatile("cp.async.cg.shared.global [%0], [%1], 16, %2;\n" :: "r"(dst), "l"(src), "r"(sz));
}
__device__ __forceinline__ void cp_commit() { asm volatile("cp.async.commit_group;\n"); }
__device__ __forceinline__ void cp_wait0()  { asm volatile("cp.async.wait_group 0;\n"); }
__device__ __forceinline__ void cp_wait1()  { asm volatile("cp.async.wait_group 1;\n"); }

// ---------------- batched rounding pass (all weights, one launch) ----------
struct RTab {
    const float* s[8];
    float* d[8];
    int end[8];          // cumulative end, in float4 units
};

__global__ void __launch_bounds__(256) round_all(RTab t, int total4)
{
    int i = blockIdx.x * 256 + threadIdx.x;
    if (i >= total4) return;
    int j = 0;
    while (i >= t.end[j]) j++;
    int off = i - (j ? t.end[j - 1] : 0);
    float4 v = ((const float4*)t.s[j])[off];
    v.x = rnd(v.x); v.y = rnd(v.y); v.z = rnd(v.z); v.w = rnd(v.w);
    ((float4*)t.d[j])[off] = v;
}

// ---------------- rmsnorm (output rounded to tf32) --------------------------
__global__ void __launch_bounds__(256) rmsnorm_kernel(
    const float* __restrict__ x, const float* __restrict__ w, float* __restrict__ y)
{
    int row = blockIdx.x;
    const float* xr = x + (size_t)row * EE;
    float vals[3];
    float s = 0.f;
#pragma unroll
    for (int i = 0; i < 3; i++) {
        vals[i] = xr[threadIdx.x + i * 256];
        s += vals[i] * vals[i];
    }
#pragma unroll
    for (int o = 16; o; o >>= 1) s += __shfl_down_sync(0xffffffffu, s, o);
    __shared__ float red[8];
    if ((threadIdx.x & 31) == 0) red[threadIdx.x >> 5] = s;
    __syncthreads();
    if (threadIdx.x < 8) {
        float t = red[threadIdx.x];
#pragma unroll
        for (int o = 4; o; o >>= 1) t += __shfl_down_sync(0xffu, t, o);
        if (threadIdx.x == 0) red[0] = t;
    }
    __syncthreads();
    float r = rsqrtf(red[0] * (1.0f / EE) + 1.1920929e-7f);
    float* yr = y + (size_t)row * EE;
#pragma unroll
    for (int i = 0; i < 3; i++) {
        int c = threadIdx.x + i * 256;
        yr[c] = rnd(vals[i] * r * w[c]);
    }
}

// ---------------- tf32 GEMM, cp.async 3-stage pipeline, templated N-tile ----
// C = A @ W^T over K, then optionally + A2 @ B2^T over K2 (dual-K accumulate)
// flags bit0: relu, bit1: round output to tf32
// blockIdx.z==1 selects (Bz,biasz,Cz) alternate problem (same A/M/N/K)
#define ST 36
#define ATILE (128*ST)      // 4608 floats

template<int NT>
__global__ void __launch_bounds__(256, 2) mma_gemm(
    const float* __restrict__ A, const float* __restrict__ B, float* __restrict__ C,
    const float* __restrict__ bias, const float* __restrict__ res,
    const float* __restrict__ inter4, const float* __restrict__ b2,
    const float* __restrict__ A2, const float* __restrict__ B2,
    int K2, int lda2, int ldb2,
    const float* __restrict__ Bz, const float* __restrict__ biasz, float* __restrict__ Cz,
    int M, int N, int K, int lda, int ldb, int ldc, int flags)
{
    constexpr int BTILE = NT * ST;
    constexpr int STG = ATILE + BTILE;
    constexpr int MT = (NT == 128) ? 2 : 1;     // m-subtiles per warp

    extern __shared__ float dyn[];
    if (blockIdx.z == 1) { B = Bz; bias = biasz; C = Cz; }

    const int tid  = threadIdx.x;
    const int lane = tid & 31, warp = tid >> 5;
    const int g = lane >> 2, t4 = lane & 3;
    const int wm = (NT == 128) ? (warp >> 1) * 32 : warp * 16;
    const int wn = (NT == 128) ? (warp & 1) * 64 : 0;
    const int mBase = blockIdx.y * 128, nBase = blockIdx.x * NT;
    const int lr = tid >> 3;            // 0..31
    const int kA = (tid & 7) * 4;       // 0,4,..,28

    const unsigned sb = (unsigned)__cvta_generic_to_shared(dyn);

    const int n1 = K >> 5, n2 = K2 >> 5, nT = n1 + n2;

    float acc[MT][8][4];
#pragma unroll
    for (int i = 0; i < MT; i++)
#pragma unroll
        for (int j = 0; j < 8; j++)
#pragma unroll
            for (int c = 0; c < 4; c++) acc[i][j][c] = 0.f;

    // issue copy of logical tile t into smem stage buf
    auto issue = [&](int t, int buf) {
        const float* Ab; const float* Bb; int la, lb, k0;
        if (t < n1) { Ab = A;  Bb = B;  la = lda;  lb = ldb;  k0 = t * 32; }
        else        { Ab = A2; Bb = B2; la = lda2; lb = ldb2; k0 = (t - n1) * 32; }
#pragma unroll
        for (int r = 0; r < 4; r++) {
            int row = lr + 32 * r;
            const float* ap = Ab + (size_t)(mBase + row) * la + k0 + kA;
            cp16(sb + (buf * STG + row * ST + kA) * 4, ap);
        }
#pragma unroll
        for (int r = 0; r < NT / 32; r++) {
            int row = lr + 32 * r;
            bool ok = (nBase + row) < N;
            const float* bp = ok ? (Bb + (size_t)(nBase + row) * lb + k0 + kA) : Bb;
            cp16z(sb + (buf * STG + ATILE + row * ST + kA) * 4, bp, ok ? 16 : 0);
        }
        cp_commit();
    };

    // prologue: stage tiles 0 and 1
    issue(0, 0);
    if (nT > 1) issue(1, 1);

    for (int t = 0; t < nT; t++) {
        if (t < nT - 1) cp_wait1(); else cp_wait0();
        __syncthreads();
        if (t + 2 < nT) issue(t + 2, (t + 2) % 3);

        const float* As = dyn + (t % 3) * STG;
        const float* Bs = As + ATILE;
#pragma unroll
        for (int kk = 0; kk < 4; kk++) {
            const int kb = kk * 8;
            unsigned a[MT][4], b[8][2];
#pragma unroll
            for (int mt = 0; mt < MT; mt++) {
                int mr = wm + mt * 16 + g;
                a[mt][0] = __float_as_uint(As[mr * ST + kb + t4]);
                a[mt][1] = __float_as_uint(As[(mr + 8) * ST + kb + t4]);
                a[mt][2] = __float_as_uint(As[mr * ST + kb + t4 + 4]);
                a[mt][3] = __float_as_uint(As[(mr + 8) * ST + kb + t4 + 4]);
            }
#pragma unroll
            for (int nt = 0; nt < 8; nt++) {
                int nc = wn + nt * 8 + g;
                b[nt][0] = __float_as_uint(Bs[nc * ST + kb + t4]);
                b[nt][1] = __float_as_uint(Bs[nc * ST + kb + t4 + 4]);
            }
#pragma unroll
            for (int mt = 0; mt < MT; mt++)
#pragma unroll
                for (int nt = 0; nt < 8; nt++)
                    mma_tf32(acc[mt][nt], a[mt], b[nt]);
        }
    }

    // --- epilogue
    const bool relu = flags & 1;
    const bool roundC = flags & 2;
#pragma unroll
    for (int mt = 0; mt < MT; mt++) {
#pragma unroll
        for (int half = 0; half < 2; half++) {
            int m = mBase + wm + mt * 16 + g + half * 8;
            float i0 = 0.f, i1 = 0.f, i2 = 0.f, i3 = 0.f;
            if (inter4) {
                const float* ip = inter4 + (size_t)m * 4;
                i0 = ip[0]; i1 = ip[1]; i2 = ip[2]; i3 = ip[3];
            }
#pragma unroll
            for (int nt = 0; nt < 8; nt++) {
#pragma unroll
                for (int c = 0; c < 2; c++) {
                    int n = nBase + wn + nt * 8 + 2 * t4 + c;
                    if (n < N) {
                        float v = acc[mt][nt][half * 2 + c];
                        if (bias) v += bias[n];
                        if (res)  v += res[(size_t)m * ldc + n];
                        if (b2) {
                            const float* bp = b2 + (size_t)n * 4;
                            v += i0 * bp[0] + i1 * bp[1] + i2 * bp[2] + i3 * bp[3];
                        }
                        if (relu) v = fmaxf(v, 0.f);
                        if (roundC) v = rnd(v);
                        C[(size_t)m * ldc + n] = v;
                    }
                }
            }
        }
    }
}

// ---------------- flash attention (cp.async K/V, pre-rounded qkv) -----------
#define QP 68
#define VP 72
#define KVST (64*QP + 64*VP)   // 8960 floats per stage
__global__ void __launch_bounds__(256, 2) flash_attn(
    const float* __restrict__ qkv, float* __restrict__ ctx)
{
    extern __shared__ float pool[];
    const unsigned sb = (unsigned)__cvta_generic_to_shared(pool);

    const int z = blockIdx.y, b = z / HH, h = z % HH;
    const float* base = qkv + (size_t)b * SS * 3 * EE + h * HD;
    const int q0 = blockIdx.x * 128;
    const int tid = threadIdx.x, lane = tid & 31, warp = tid >> 5;
    const int g = lane >> 2, t4 = lane & 3;
    const float qscale = 0.125f * 1.4426950408889634f;  // 1/sqrt(64) * log2(e)

    // ---- stage Q (scaled, tf32) through smem, then load register fragments
#pragma unroll
    for (int r = 0; r < 8; r++) {
        int idx = tid + r * 256;           // 0..2047
        int row = idx >> 4, c4 = (idx & 15) * 4;
        float4 v = *(const float4*)(base + (size_t)(q0 + row) * 3 * EE + c4);
        float4 w;
        w.x = rnd(v.x * qscale);
        w.y = rnd(v.y * qscale);
        w.z = rnd(v.z * qscale);
        w.w = rnd(v.w * qscale);
        *(float4*)(pool + row * QP + c4) = w;
    }
    __syncthreads();
    unsigned qf[8][4];
    const int wq = warp * 16;
#pragma unroll
    for (int kc = 0; kc < 8; kc++) {
        qf[kc][0] = __float_as_uint(pool[(wq + g)     * QP + kc * 8 + t4]);
        qf[kc][1] = __float_as_uint(pool[(wq + g + 8) * QP + kc * 8 + t4]);
        qf[kc][2] = __float_as_uint(pool[(wq + g)     * QP + kc * 8 + t4 + 4]);
        qf[kc][3] = __float_as_uint(pool[(wq + g + 8) * QP + kc * 8 + t4 + 4]);
    }
    __syncthreads();

    float o[8][4];
#pragma unroll
    for (int v = 0; v < 8; v++)
#pragma unroll
        for (int c = 0; c < 4; c++) o[v][c] = 0.f;
    float m0 = -INFINITY, m1 = -INFINITY, l0 = 0.f, l1 = 0.f;

    const int Le = (lane & 28) | (t4 >> 1);
    const int Lo = Le | 2;
    const bool odd = t4 & 1;

    const int frow = tid >> 4, fseg = (tid & 15) * 4;   // K/V copy mapping

    // prologue: issue K/V tile 0
#pragma unroll
    for (int r = 0; r < 4; r++) {
        int row = frow + r * 16;
        const float* kp = base + EE     + (size_t)row * 3 * EE + fseg;
        const float* vp = base + 2 * EE + (size_t)row * 3 * EE + fseg;
        cp16(sb + (row * QP + fseg) * 4, kp);
        cp16(sb + (64 * QP + row * VP + fseg) * 4, vp);
    }
    cp_commit();

    for (int kt = 0; kt < SS / 64; kt++) {
        cp_wait0();
        __syncthreads();
        if (kt + 1 < SS / 64) {
            const int nbuf = (kt + 1) & 1;
#pragma unroll
            for (int r = 0; r < 4; r++) {
                int row = frow + r * 16;
                const float* kp = base + EE     + (size_t)((kt + 1) * 64 + row) * 3 * EE + fseg;
                const float* vp = base + 2 * EE + (size_t)((kt + 1) * 64 + row) * 3 * EE + fseg;
                cp16(sb + (nbuf * KVST + row * QP + fseg) * 4, kp);
                cp16(sb + (nbuf * KVST + 64 * QP + row * VP + fseg) * 4, vp);
            }
            cp_commit();
        }
        const float* Ks = pool + (kt & 1) * KVST;
        const float* Vs = Ks + 64 * QP;

        // ---- scores
        float s[8][4];
#pragma unroll
        for (int j = 0; j < 8; j++)
#pragma unroll
            for (int c = 0; c < 4; c++) s[j][c] = 0.f;
#pragma unroll
        for (int j = 0; j < 8; j++) {
#pragma unroll
            for (int kc = 0; kc < 8; kc++) {
                unsigned bfr[2];
                bfr[0] = __float_as_uint(Ks[(j * 8 + g) * QP + kc * 8 + t4]);
                bfr[1] = __float_as_uint(Ks[(j * 8 + g) * QP + kc * 8 + t4 + 4]);
                mma_tf32(s[j], qf[kc], bfr);
            }
        }

        // ---- online softmax (log2 domain)
        float r0 = -INFINITY, r1 = -INFINITY;
#pragma unroll
        for (int j = 0; j < 8; j++) {
            r0 = fmaxf(r0, fmaxf(s[j][0], s[j][1]));
            r1 = fmaxf(r1, fmaxf(s[j][2], s[j][3]));
        }
        r0 = fmaxf(r0, __shfl_xor_sync(0xffffffffu, r0, 1));
        r0 = fmaxf(r0, __shfl_xor_sync(0xffffffffu, r0, 2));
        r1 = fmaxf(r1, __shfl_xor_sync(0xffffffffu, r1, 1));
        r1 = fmaxf(r1, __shfl_xor_sync(0xffffffffu, r1, 2));
        float m0n = fmaxf(m0, r0), m1n = fmaxf(m1, r1);
        float c0 = exp2f(m0 - m0n), c1 = exp2f(m1 - m1n);
        l0 *= c0; l1 *= c1;
#pragma unroll
        for (int v = 0; v < 8; v++) {
            o[v][0] *= c0; o[v][1] *= c0;
            o[v][2] *= c1; o[v][3] *= c1;
        }
        m0 = m0n; m1 = m1n;
#pragma unroll
        for (int j = 0; j < 8; j++) {
            s[j][0] = exp2f(s[j][0] - m0);
            s[j][1] = exp2f(s[j][1] - m0);
            s[j][2] = exp2f(s[j][2] - m1);
            s[j][3] = exp2f(s[j][3] - m1);
            l0 += s[j][0] + s[j][1];
            l1 += s[j][2] + s[j][3];
        }

        // ---- P.V
#pragma unroll
        for (int j = 0; j < 8; j++) {
            float e0 = __shfl_sync(0xffffffffu, s[j][0], Le);
            float f0 = __shfl_sync(0xffffffffu, s[j][1], Le);
            float e1 = __shfl_sync(0xffffffffu, s[j][2], Le);
            float f1 = __shfl_sync(0xffffffffu, s[j][3], Le);
            float e2 = __shfl_sync(0xffffffffu, s[j][0], Lo);
            float f2 = __shfl_sync(0xffffffffu, s[j][1], Lo);
            float e3 = __shfl_sync(0xffffffffu, s[j][2], Lo);
            float f3 = __shfl_sync(0xffffffffu, s[j][3], Lo);
            unsigned pa[4];
            pa[0] = f2tf32(odd ? f0 : e0);
            pa[1] = f2tf32(odd ? f1 : e1);
            pa[2] = f2tf32(odd ? f2 : e2);
            pa[3] = f2tf32(odd ? f3 : e3);
#pragma unroll
            for (int v = 0; v < 8; v++) {
                unsigned bfr[2];
                bfr[0] = __float_as_uint(Vs[(j * 8 + t4)     * VP + v * 8 + g]);
                bfr[1] = __float_as_uint(Vs[(j * 8 + t4 + 4) * VP + v * 8 + g]);
                mma_tf32(o[v], pa, bfr);
            }
        }
    }

    // ---- finalize (rounded: ctx feeds out_proj GEMM)
    l0 += __shfl_xor_sync(0xffffffffu, l0, 1);
    l0 += __shfl_xor_sync(0xffffffffu, l0, 2);
    l1 += __shfl_xor_sync(0xffffffffu, l1, 1);
    l1 += __shfl_xor_sync(0xffffffffu, l1, 2);
    float inv0 = 1.f / l0, inv1 = 1.f / l1;
    int row0 = q0 + wq + g, row1 = row0 + 8;
    float* c0p = ctx + ((size_t)(b * SS + row0)) * EE + h * HD;
    float* c1p = ctx + ((size_t)(b * SS + row1)) * EE + h * HD;
#pragma unroll
    for (int v = 0; v < 8; v++) {
        int col = v * 8 + 2 * t4;
        float2 w0 = make_float2(rnd(o[v][0] * inv0), rnd(o[v][1] * inv0));
        float2 w1 = make_float2(rnd(o[v][2] * inv1), rnd(o[v][3] * inv1));
        *(float2*)(c0p + col) = w0;
        *(float2*)(c1p + col) = w1;
    }
}

// ---------------- small helper kernels -------------------------------------
__global__ void build_WBt(const float* __restrict__ hB_w2,
                          const float* __restrict__ hB_b2,
                          float* __restrict__ WBt)
{
    int idx = blockIdx.x * 256 + threadIdx.x;
    if (idx >= (RR * HID + RR) * EE) return;
    int n = idx / EE, e = idx % EE;
    float val;
    if (n < RR * HID) {
        int r = n >> 7, h = n & 127;
        val = hB_w2[((size_t)(r * EE + e)) * HID + h];
    } else {
        val = hB_b2[(n - RR * HID) * EE + e];
    }
    WBt[idx] = rnd(val);
}

// merged: inter[m,r] = hB[m,:].v[m,r*128:] + v[m,512+r];  u[m,r*128+h] = inter*hA (rounded)
__global__ void __launch_bounds__(256) interu_kernel(
    const float* __restrict__ v, const float* __restrict__ hB,
    const float* __restrict__ hA, float* __restrict__ inter, float* __restrict__ u)
{
    int wtok = (blockIdx.x * 256 + threadIdx.x) >> 5;
    int lane = threadIdx.x & 31;
    if (wtok >= MM) return;
    const float* vr = v + (size_t)wtok * (RR * HID + RR);
    const float* br = hB + (size_t)wtok * HID;
    float hb[4], ha[4];
#pragma unroll
    for (int j = 0; j < 4; j++) {
        hb[j] = br[lane + j * 32];
        ha[j] = hA[(size_t)wtok * HID + lane + j * 32];
    }
    float iv[RR];
#pragma unroll
    for (int r = 0; r < RR; r++) {
        float s = 0.f;
#pragma unroll
        for (int j = 0; j < 4; j++) s += hb[j] * vr[r * HID + lane + j * 32];
#pragma unroll
        for (int o = 16; o; o >>= 1) s += __shfl_xor_sync(0xffffffffu, s, o);
        iv[r] = s + vr[RR * HID + r];
    }
    if (lane < RR) inter[wtok * RR + lane] = iv[lane];
    float* ur = u + (size_t)wtok * RR * HID;
#pragma unroll
    for (int r = 0; r < RR; r++)
#pragma unroll
        for (int j = 0; j < 4; j++)
            ur[r * HID + lane + j * 32] = rnd(iv[r] * ha[j]);
}

// ---------------- launch ----------------------------------------------------
extern "C" void kernel_launch(void* const* d_in, const int* in_sizes, int n_in,
                              void* d_out, int out_size)
{
    const float* src       = (const float*)d_in[0];
    const float* task      = (const float*)d_in[1];
    const float* norm1_w   = (const float*)d_in[2];
    const float* norm2_w   = (const float*)d_in[3];
    const float* in_proj_w = (const float*)d_in[4];
    const float* out_proj_w= (const float*)d_in[5];
    const float* ffn1_w    = (const float*)d_in[6];
    const float* ffn1_b    = (const float*)d_in[7];
    const float* ffn2_w    = (const float*)d_in[8];
    const float* ffn2_b    = (const float*)d_in[9];
    const float* hA_w1     = (const float*)d_in[10];
    const float* hA_b1     = (const float*)d_in[11];
    const float* hA_w2     = (const float*)d_in[12];
    const float* hA_b2     = (const float*)d_in[13];
    const float* hB_w1     = (const float*)d_in[14];
    const float* hB_b1     = (const float*)d_in[15];
    const float* hB_w2     = (const float*)d_in[16];
    const float* hB_b2     = (const float*)d_in[17];
    float* out = (float*)d_out;

    float *x1, *qkv, *ctx, *src2, *x2, *hA, *hB, *WBt, *v, *inter, *u, *hbuf;
    float *r_task, *r_inproj, *r_outproj, *r_ffn1, *r_ffn2, *r_hAw2, *r_hw1;
    cudaGetSymbolAddress((void**)&x1,   g_x1);
    cudaGetSymbolAddress((void**)&qkv,  g_qkv);
    cudaGetSymbolAddress((void**)&ctx,  g_ctx);
    cudaGetSymbolAddress((void**)&src2, g_src2);
    cudaGetSymbolAddress((void**)&x2,   g_x2);
    cudaGetSymbolAddress((void**)&hA,   g_hA);
    cudaGetSymbolAddress((void**)&hB,   g_hB);
    cudaGetSymbolAddress((void**)&WBt,  g_WBt);
    cudaGetSymbolAddress((void**)&v,    g_v);
    cudaGetSymbolAddress((void**)&inter,g_int);
    cudaGetSymbolAddress((void**)&u,    g_u);
    cudaGetSymbolAddress((void**)&hbuf, g_h);
    cudaGetSymbolAddress((void**)&r_task,   g_r_task);
    cudaGetSymbolAddress((void**)&r_inproj, g_r_inproj);
    cudaGetSymbolAddress((void**)&r_outproj,g_r_outproj);
    cudaGetSymbolAddress((void**)&r_ffn1,   g_r_ffn1);
    cudaGetSymbolAddress((void**)&r_ffn2,   g_r_ffn2);
    cudaGetSymbolAddress((void**)&r_hAw2,   g_r_hAw2);
    cudaGetSymbolAddress((void**)&r_hw1,    g_r_hw1);

    const int DS128 = 3 * (ATILE + 128 * ST) * 4;   // 110592 B
    const int DS64  = 3 * (ATILE + 64 * ST) * 4;    //  82944 B
    const int FS = 2 * KVST * 4;                    //  71680 B
    cudaFuncSetAttribute(mma_gemm<128>, cudaFuncAttributeMaxDynamicSharedMemorySize, DS128);
    cudaFuncSetAttribute(mma_gemm<64>,  cudaFuncAttributeMaxDynamicSharedMemorySize, DS64);
    cudaFuncSetAttribute(flash_attn,    cudaFuncAttributeMaxDynamicSharedMemorySize, FS);

    // 0) pre-round all GEMM operands to tf32 (one launch)
    {
        RTab t;
        const float* ss[8] = {task, in_proj_w, out_proj_w, ffn1_w, ffn2_w, hA_w2, hA_w1, hB_w1};
        float* dd[8] = {r_task, r_inproj, r_outproj, r_ffn1, r_ffn2, r_hAw2, r_hw1, r_hw1 + HID * TT};
        int nn[8] = {MM * TT / 4, 3 * EE * EE / 4, EE * EE / 4, FF * EE / 4,
                     EE * FF / 4, FF * RR * HID / 4, HID * TT / 4, HID * TT / 4};
        int cum = 0;
        for (int j = 0; j < 8; j++) { t.s[j] = ss[j]; t.d[j] = dd[j]; cum += nn[j]; t.end[j] = cum; }
        round_all<<<(cum + 255) / 256, 256>>>(t, cum);
    }

    // 1) x1 = rmsnorm(src, norm1_w) (rounded)
    rmsnorm_kernel<<<MM, 256>>>(src, norm1_w, x1);

    // 2) qkv = x1 @ in_proj^T (rounded out)
    mma_gemm<128><<<dim3(18, 32, 1), 256, DS128>>>(
        x1, r_inproj, qkv, nullptr, nullptr, nullptr, nullptr,
        nullptr, nullptr, 0, 0, 0, nullptr, nullptr, nullptr,
        MM, 3 * EE, EE, EE, EE, 3 * EE, 2);

    // 3) flash attention -> ctx (rounded)
    flash_attn<<<dim3(SS / 128, BB * HH), 256, FS>>>(qkv, ctx);

    // 4) src2 = src + ctx @ out_proj^T  (N=768, NT=64 -> 384 CTAs)
    mma_gemm<64><<<dim3(12, 32, 1), 256, DS64>>>(
        ctx, r_outproj, src2, nullptr, src, nullptr, nullptr,
        nullptr, nullptr, 0, 0, 0, nullptr, nullptr, nullptr,
        MM, EE, EE, EE, EE, EE, 0);

    // 5) x2 = rmsnorm(src2) (rounded)
    rmsnorm_kernel<<<MM, 256>>>(src2, norm2_w, x2);

    // 6) hypernet hiddens hA & hB in one launch (z selects problem; NT=64 -> 128 CTAs)
    mma_gemm<64><<<dim3(2, 32, 2), 256, DS64>>>(
        r_task, r_hw1, hA, hA_b1, nullptr, nullptr, nullptr,
        nullptr, nullptr, 0, 0, 0,
        r_hw1 + HID * TT, hB_b1, hB,
        MM, HID, TT, TT, TT, HID, 1);

    // 7) rearranged B-side weights (rounded)
    build_WBt<<<((RR * HID + RR) * EE + 255) / 256, 256>>>(hB_w2, hB_b2, WBt);

    // 8) v = x2 @ WBt^T  [4096, 516]  (NT=64 -> 288 CTAs)
    mma_gemm<64><<<dim3(9, 32, 1), 256, DS64>>>(
        x2, WBt, v, nullptr, nullptr, nullptr, nullptr,
        nullptr, nullptr, 0, 0, 0, nullptr, nullptr, nullptr,
        MM, RR * HID + RR, EE, EE, EE, RR * HID + RR, 0);

    // 9) inter + u (rounded)
    interu_kernel<<<MM / 8, 256>>>(v, hB, hA, inter, u);

    // 10) fused FFN1 + LoRA expand: hbuf = relu(x2@ffn1^T + u@hAw2^T + ffn1_b + lora_b), rounded
    mma_gemm<128><<<dim3(24, 32, 1), 256, DS128>>>(
        x2, r_ffn1, hbuf, ffn1_b, nullptr, inter, hA_b2,
        u, r_hAw2, RR * HID, RR * HID, RR * HID,
        nullptr, nullptr, nullptr,
        MM, FF, EE, EE, EE, FF, 3);

    // 11) out = src2 + hbuf @ ffn2^T + ffn2_b  (N=768, NT=64 -> 384 CTAs)
    mma_gemm<64><<<dim3(12, 32, 1), 256, DS64>>>(
        hbuf, r_ffn2, out, ffn2_b, src2, nullptr, nullptr,
        nullptr, nullptr, 0, 0, 0, nullptr, nullptr, nullptr,
        MM, EE, FF, FF, FF, EE, 0);
}